// round 9
// baseline (speedup 1.0000x reference)
#include <cuda_runtime.h>
#include <cuda_bf16.h>
#include <cstdint>
#include <cstddef>

// Problem constants
#define BB   64
#define TT   256
#define DIN  256
#define HH   1024
#define G4   4096
#define NCTA 128

// persist smem layout (bf16 elems)
#define WS2  1032            // weight row stride (1024 + 8)
#define AS3  520             // h chunk row stride (512 + 8)
#define PERSIST_SMEM (64*WS2*2 + 2*32*AS3*2)   // 132096 + 66560 = 198656

// proj smem layout
#define PS    40             // row stride elems (32 + 8)
#define PTILE (128*PS)       // elems per stage per operand
#define PROJ_SMEM (3*PTILE*2*2 + 512)

// flag padding: 64 u32 = 256B per flag -> distinct L2 slices
#define FPAD 64

// ---------------------------------------------------------------------------
// Scratch (allocation-free: __device__ globals)
// ---------------------------------------------------------------------------
__device__ __align__(128) float          g_xg[(size_t)BB * TT * G4];
__device__ __align__(128) __nv_bfloat16  g_hs_a[(size_t)BB * TT * HH];
__device__ __align__(128) __nv_bfloat16  g_hs_b[(size_t)BB * TT * HH];
__device__ __align__(128) __nv_bfloat16  g_hbuf[2][BB * HH];
__device__ __align__(128) __nv_bfloat16  g_xb[(size_t)BB * TT * DIN];
__device__ __align__(128) __nv_bfloat16  g_wb[(size_t)(G4 * DIN + 2 * G4 * HH)];
__device__ __align__(128) unsigned       g_flags[NCTA * FPAD];

// ---------------------------------------------------------------------------
// helpers
// ---------------------------------------------------------------------------
__device__ __forceinline__ uint32_t packbf(float lo, float hi) {
    uint32_t r;
    asm("cvt.rn.bf16x2.f32 %0, %1, %2;" : "=r"(r) : "f"(hi), "f"(lo));
    return r;
}

__device__ __forceinline__ void mma_bf16(float c[4], const uint32_t a[4],
                                         uint32_t b0, uint32_t b1) {
    asm volatile(
        "mma.sync.aligned.m16n8k16.row.col.f32.bf16.bf16.f32 "
        "{%0,%1,%2,%3}, {%4,%5,%6,%7}, {%8,%9}, {%0,%1,%2,%3};\n"
        : "+f"(c[0]), "+f"(c[1]), "+f"(c[2]), "+f"(c[3])
        : "r"(a[0]), "r"(a[1]), "r"(a[2]), "r"(a[3]), "r"(b0), "r"(b1));
}

__device__ __forceinline__ uint32_t smem_u32(const void* p) {
    return (uint32_t)__cvta_generic_to_shared(p);
}

__device__ __forceinline__ void ldsm4(uint32_t r[4], uint32_t addr) {
    asm volatile("ldmatrix.sync.aligned.m8n8.x4.shared.b16 {%0,%1,%2,%3}, [%4];\n"
                 : "=r"(r[0]), "=r"(r[1]), "=r"(r[2]), "=r"(r[3]) : "r"(addr));
}

__device__ __forceinline__ void cp16(uint32_t daddr, const void* src) {
    asm volatile("cp.async.cg.shared.global [%0], [%1], 16;\n"
                 :: "r"(daddr), "l"(src));
}
#define CP_COMMIT() asm volatile("cp.async.commit_group;\n")
template <int N> __device__ __forceinline__ void cp_wait() {
    asm volatile("cp.async.wait_group %0;\n" :: "n"(N));
}

__device__ __forceinline__ unsigned ld_acq(const unsigned* p) {
    unsigned v;
    asm volatile("ld.acquire.gpu.u32 %0, [%1];" : "=r"(v) : "l"(p));
    return v;
}
__device__ __forceinline__ void st_rel(unsigned* p, unsigned v) {
    asm volatile("st.release.gpu.u32 [%0], %1;" :: "l"(p), "r"(v));
}

__device__ __forceinline__ float sigf(float x) { return 1.0f / (1.0f + __expf(-x)); }

// ---------------------------------------------------------------------------
// Convert stage A: x -> bf16
// ---------------------------------------------------------------------------
__global__ void convA_kernel(const float* __restrict__ x)
{
    int i = blockIdx.x * blockDim.x + threadIdx.x;
    if (i >= (BB * TT * DIN) / 4) return;
    float4 v = ((const float4*)x)[i];
    uint32_t* d = (uint32_t*)g_xb + (size_t)i * 2;
    d[0] = packbf(v.x, v.y);
    d[1] = packbf(v.z, v.w);
}

// ---------------------------------------------------------------------------
// Convert stage B: w_ih0/1/2 -> bf16, and zero the sync flags (per launch)
// ---------------------------------------------------------------------------
__global__ void convB_kernel(const float* __restrict__ w0,
                             const float* __restrict__ w1,
                             const float* __restrict__ w2)
{
    int i = blockIdx.x * blockDim.x + threadIdx.x;
    if (i < NCTA * FPAD) g_flags[i] = 0;
    if (i < (G4 * DIN) / 4) {
        float4 v = ((const float4*)w0)[i];
        uint32_t* d = (uint32_t*)g_wb + (size_t)i * 2;
        d[0] = packbf(v.x, v.y);
        d[1] = packbf(v.z, v.w);
    }
    if (i < (G4 * HH) / 4) {
        float4 v = ((const float4*)w1)[i];
        uint32_t* d = (uint32_t*)(g_wb + (size_t)G4 * DIN) + (size_t)i * 2;
        d[0] = packbf(v.x, v.y);
        d[1] = packbf(v.z, v.w);
        float4 u = ((const float4*)w2)[i];
        uint32_t* e = (uint32_t*)(g_wb + (size_t)G4 * (DIN + HH)) + (size_t)i * 2;
        e[0] = packbf(u.x, u.y);
        e[1] = packbf(u.z, u.w);
    }
}

// ---------------------------------------------------------------------------
// Persistent recurrent kernel: 128 CTAs = 2 batch-halves x 64 unit-groups.
// CTA (bh, ug): batches bh*32..+31, hidden units ug*16..+15.
// 512 threads, 16 warps (2M x 8N). Tile col c = 4*unit + gate (gate
// interleave) so a lane pair holds all 4 gates of one (batch,unit) ->
// pointwise exchange via 2 shfl.bfly, no SMEM roundtrip.
// Weights [64][1024] bf16 stationary in SMEM; h via cp.async (2 chunks).
// Monotonic padded flags. t=0 skips wait/load/GEMM (h0 == 0).
// ---------------------------------------------------------------------------
__global__ void __launch_bounds__(512, 1)
persist_kernel(const float* __restrict__ Whh, int hs_sel, unsigned base)
{
    extern __shared__ __align__(16) unsigned char smem[];
    __nv_bfloat16* Wsm = (__nv_bfloat16*)smem;            // [64][WS2]
    __nv_bfloat16* Asm = Wsm + 64 * WS2;                  // [2][32][AS3]

    const int tid  = threadIdx.x;
    const int cta  = blockIdx.x;
    const int bh   = cta >> 6;
    const int ug   = cta & 63;
    const int j0   = ug * 16;
    const int b0   = bh * 32;
    const int wid  = tid >> 5, lane = tid & 31;
    const int g    = lane >> 2, tq = lane & 3;
    const int wm   = (wid >> 3) * 16;     // 0 / 16
    const int wn   = (wid & 7) * 8;       // 0..56
    const int lrow = lane & 15;
    const int lhi  = (lane >> 4) * 8;
    const int bn   = wn + (lane & 7);     // B ldsm row (tile col)
    const int bk   = (lane >> 3) * 8;     // B ldsm k offset (0/8/16/24)

    // pointwise identity: lane pair (tq, tq^1) owns unit u; even lane row
    // wm+g, odd lane row wm+g+8.
    const int odd  = lane & 1;
    const int u    = (wid & 7) * 2 + (tq >> 1);
    const int pb   = b0 + wm + g + (odd ? 8 : 0);   // batch index
    const int pj   = j0 + u;                        // hidden unit index

    const unsigned* poll_p = &g_flags[(bh * 64 + (tid & 63)) * FPAD];
    unsigned* my_flag = &g_flags[(bh * 64 + ug) * FPAD];

    // ---- gather + convert weights (once per layer) ----
    // SMEM row n = tile col c: gate = c & 3, unit = c >> 2.
    for (int idx = tid; idx < 64 * 256; idx += 512) {
        int n = idx >> 8;  int k4 = (idx & 255) * 4;
        int gate = n & 3, uu = n >> 2;
        float4 w = *(const float4*)(Whh + (size_t)(gate * HH + j0 + uu) * HH + k4);
        uint32_t* dst = (uint32_t*)(Wsm + n * WS2 + k4);
        dst[0] = packbf(w.x, w.y);
        dst[1] = packbf(w.z, w.w);
    }
    __syncthreads();

    float cst = 0.0f;   // cell state for (pb, pj)

    for (int t = 0; t < TT; t++) {
        const __nv_bfloat16* __restrict__ hin  = g_hbuf[t & 1];
        __nv_bfloat16* __restrict__       hout = g_hbuf[(t + 1) & 1];

        // xg prefetch for this thread's (pb, pj): 4 gate planes
        const float* xp = g_xg + ((size_t)pb * TT + t) * G4 + pj;
        float x0 = xp[0], x1 = xp[HH], x2 = xp[2 * HH], x3 = xp[3 * HH];

        float acc[4] = {0.0f, 0.0f, 0.0f, 0.0f};

        if (t > 0) {
            // wait for all producers of this batch half (padded flags)
            if (tid < 64) {
                while ((int)ld_acq(poll_p) < (int)(base + t)) {}
            }
            __syncthreads();

            // issue both h-chunk loads (512 K each, one group per chunk)
#pragma unroll
            for (int kc = 0; kc < 2; kc++) {
#pragma unroll
                for (int r = 0; r < 4; r++) {
                    int lin = tid + r * 512;
                    int row = lin >> 6, c8 = (lin & 63) * 8;
                    cp16(smem_u32(Asm + kc * (32 * AS3) + row * AS3 + c8),
                         hin + (size_t)(b0 + row) * HH + kc * 512 + c8);
                }
                CP_COMMIT();
            }

            auto compute = [&](int kc) {
                const __nv_bfloat16* Ab = Asm + kc * (32 * AS3);
                const __nv_bfloat16* Wb = Wsm + kc * 512;
#pragma unroll
                for (int qp = 0; qp < 16; qp++) {
                    uint32_t bq[4], a0[4], a1[4];
                    // B: n8 x k32 in one ldsm.x4 (mats: k0-7,k8-15,k16-23,k24-31)
                    ldsm4(bq, smem_u32(Wb + bn * WS2 + qp * 32 + bk));
                    ldsm4(a0, smem_u32(Ab + (wm + lrow) * AS3 + qp * 32 + lhi));
                    ldsm4(a1, smem_u32(Ab + (wm + lrow) * AS3 + qp * 32 + 16 + lhi));
                    mma_bf16(acc, a0, bq[0], bq[1]);
                    mma_bf16(acc, a1, bq[2], bq[3]);
                }
            };

            cp_wait<1>(); __syncthreads(); compute(0);
            cp_wait<0>(); __syncthreads(); compute(1);
        }

        // ---- gate exchange via shfl (lane pair holds i,f | g,o) ----
        // even lane (tq even): acc = {i row, f row, i row+8, f row+8}
        // odd  lane (tq odd ): acc = {g row, o row, g row+8, o row+8}
        float sA = odd ? acc[0] : acc[2];
        float sB = odd ? acc[1] : acc[3];
        float rx0 = __shfl_xor_sync(0xffffffffu, sA, 1);
        float rx1 = __shfl_xor_sync(0xffffffffu, sB, 1);

        float iv, fv, gv, ov;
        if (!odd) { iv = acc[0]; fv = acc[1]; gv = rx0;    ov = rx1;    }
        else      { iv = rx0;    fv = rx1;    gv = acc[2]; ov = acc[3]; }
        iv += x0; fv += x1; gv += x2; ov += x3;

        float cn = sigf(fv) * cst + sigf(iv) * tanhf(gv);
        float hn = sigf(ov) * tanhf(cn);
        cst = cn;

        __nv_bfloat16 hb = __float2bfloat16(hn);
        hout[(size_t)pb * HH + pj] = hb;
        __syncthreads();

        if (tid == 0) {
            __threadfence();
            st_rel(my_flag, base + (unsigned)t + 1);
        }

        // hidden-sequence store off the critical path (after flag release)
        if (hs_sel) {
            __nv_bfloat16* __restrict__ hs = (hs_sel == 1) ? g_hs_a : g_hs_b;
            hs[((size_t)pb * TT + t) * HH + pj] = hb;
        }
    }
}

// ---------------------------------------------------------------------------
// Projection GEMM (all-bf16, cp.async 3-stage, ldmatrix, 128x128 tile):
// g_xg[M,4096] = A[M,K] @ W[4096,K]^T + b1 + b2,  M = B*T = 16384
// ---------------------------------------------------------------------------
__global__ void __launch_bounds__(256, 2)
proj_kernel(int a_sel, size_t w_off, const float* __restrict__ b1v,
            const float* __restrict__ b2v, int K)
{
    extern __shared__ __align__(16) unsigned char smem[];
    __nv_bfloat16* Asb = (__nv_bfloat16*)smem;    // [3][128][PS]
    __nv_bfloat16* Bsb = Asb + 3 * PTILE;         // [3][128][PS]
    float*         bsm = (float*)(Bsb + 3 * PTILE);

    const __nv_bfloat16* __restrict__ A =
        (a_sel == 0) ? g_xb : (a_sel == 1 ? g_hs_a : g_hs_b);
    const __nv_bfloat16* __restrict__ W = g_wb + w_off;

    const int tid  = threadIdx.x;
    const int m0   = blockIdx.y * 128;
    const int n0   = blockIdx.x * 128;
    const int warp = tid >> 5, lane = tid & 31;
    const int g    = lane >> 2, tq = lane & 3;
    const int wmw  = (warp >> 1) * 32;    // 0/32/64/96
    const int wnw  = (warp & 1) * 64;     // 0/64
    const int lrow = lane & 15;
    const int lhi  = (lane >> 4) * 8;

    if (tid < 128) bsm[tid] = b1v[n0 + tid] + b2v[n0 + tid];

    float acc[2][8][4];
#pragma unroll
    for (int i = 0; i < 2; i++)
#pragma unroll
        for (int j = 0; j < 8; j++)
#pragma unroll
            for (int q = 0; q < 4; q++) acc[i][j][q] = 0.0f;

    auto load = [&](int kc, int st) {
#pragma unroll
        for (int r = 0; r < 2; r++) {
            int lin = tid + r * 256;
            int row = lin >> 2, c8 = (lin & 3) * 8;
            cp16(smem_u32(Asb + st * PTILE + row * PS + c8),
                 A + (size_t)(m0 + row) * K + kc * 32 + c8);
            cp16(smem_u32(Bsb + st * PTILE + row * PS + c8),
                 W + (size_t)(n0 + row) * K + kc * 32 + c8);
        }
    };

    auto compute = [&](int st) {
        const __nv_bfloat16* Ab = Asb + st * PTILE;
        const __nv_bfloat16* Bb = Bsb + st * PTILE;
#pragma unroll
        for (int q = 0; q < 2; q++) {
            uint32_t af[2][4], bf4[4][4];
            ldsm4(af[0], smem_u32(Ab + (wmw + lrow) * PS + q * 16 + lhi));
            ldsm4(af[1], smem_u32(Ab + (wmw + 16 + lrow) * PS + q * 16 + lhi));
#pragma unroll
            for (int jn = 0; jn < 4; jn++)
                ldsm4(bf4[jn], smem_u32(Bb + (wnw + jn * 16 + lrow) * PS + q * 16 + lhi));
#pragma unroll
            for (int i = 0; i < 2; i++)
#pragma unroll
                for (int j8 = 0; j8 < 8; j8++)
                    mma_bf16(acc[i][j8], af[i],
                             bf4[j8 >> 1][j8 & 1], bf4[j8 >> 1][(j8 & 1) + 2]);
        }
    };

    const int nk = K / 32;
    load(0, 0); CP_COMMIT();
    load(1, 1); CP_COMMIT();
#pragma unroll 1
    for (int kc = 0; kc < nk; kc++) {
        cp_wait<1>();
        __syncthreads();
        if (kc + 2 < nk) load(kc + 2, (kc + 2) % 3);
        CP_COMMIT();
        compute(kc % 3);
    }

    // epilogue: add biases, store fp32 to g_xg
#pragma unroll
    for (int i = 0; i < 2; i++)
#pragma unroll
        for (int j8 = 0; j8 < 8; j8++) {
            int row  = m0 + wmw + i * 16 + g;
            int lcol = wnw + j8 * 8 + 2 * tq;
            int col  = n0 + lcol;
            float bb0 = bsm[lcol], bb1 = bsm[lcol + 1];
            g_xg[(size_t)row * G4 + col]           = acc[i][j8][0] + bb0;
            g_xg[(size_t)row * G4 + col + 1]       = acc[i][j8][1] + bb1;
            g_xg[(size_t)(row + 8) * G4 + col]     = acc[i][j8][2] + bb0;
            g_xg[(size_t)(row + 8) * G4 + col + 1] = acc[i][j8][3] + bb1;
        }
}

// ---------------------------------------------------------------------------
// Final FC: out[b] = dot(h_final[b,:], fc_w) + fc_b[0];  h_final = g_hbuf[0]
// ---------------------------------------------------------------------------
__global__ void fc_kernel(const float* __restrict__ fw,
                          const float* __restrict__ fb,
                          float* __restrict__ out)
{
    __shared__ float red[8];
    int b   = blockIdx.x;
    int tid = threadIdx.x;
    const __nv_bfloat16* __restrict__ hr = g_hbuf[0] + b * HH;

    float s = 0.0f;
    for (int j = tid; j < HH; j += blockDim.x)
        s += __bfloat162float(hr[j]) * fw[j];

#pragma unroll
    for (int o = 16; o > 0; o >>= 1) s += __shfl_down_sync(0xffffffffu, s, o);
    if ((tid & 31) == 0) red[tid >> 5] = s;
    __syncthreads();
    if (tid == 0) {
        float tot = 0.0f;
        for (int w = 0; w < 8; w++) tot += red[w];
        out[b] = tot + fb[0];
    }
}

// ---------------------------------------------------------------------------
// Launch sequence (graph-capturable, kernels only):
// convA, convB, (proj, persist) x3, fc
// ---------------------------------------------------------------------------
extern "C" void kernel_launch(void* const* d_in, const int* in_sizes, int n_in,
                              void* d_out, int out_size)
{
    const float* x       = (const float*)d_in[0];
    const float* w_ih[3] = { (const float*)d_in[1], (const float*)d_in[5], (const float*)d_in[9]  };
    const float* w_hh[3] = { (const float*)d_in[2], (const float*)d_in[6], (const float*)d_in[10] };
    const float* b_ih[3] = { (const float*)d_in[3], (const float*)d_in[7], (const float*)d_in[11] };
    const float* b_hh[3] = { (const float*)d_in[4], (const float*)d_in[8], (const float*)d_in[12] };
    const float* fc_w    = (const float*)d_in[13];
    const float* fc_b    = (const float*)d_in[14];
    float* out = (float*)d_out;

    cudaFuncSetAttribute(persist_kernel,
                         cudaFuncAttributeMaxDynamicSharedMemorySize, PERSIST_SMEM);
    cudaFuncSetAttribute(proj_kernel,
                         cudaFuncAttributeMaxDynamicSharedMemorySize, PROJ_SMEM);

    convA_kernel<<<(BB * TT * DIN / 4 + 255) / 256, 256>>>(x);
    convB_kernel<<<(G4 * HH / 4 + 255) / 256, 256>>>(w_ih[0], w_ih[1], w_ih[2]);

    const int    a_sel[3]  = { 0, 1, 2 };
    const int    hs_sel[3] = { 1, 2, 0 };
    const int    K_in[3]   = { DIN, HH, HH };
    const size_t w_off[3]  = { 0, (size_t)G4 * DIN, (size_t)G4 * (DIN + HH) };

    dim3 pgrid(32, 128);

    for (int l = 0; l < 3; l++) {
        proj_kernel<<<pgrid, 256, PROJ_SMEM>>>(a_sel[l], w_off[l], b_ih[l], b_hh[l], K_in[l]);
        persist_kernel<<<NCTA, 512, PERSIST_SMEM>>>(w_hh[l], hs_sel[l],
                                                    (unsigned)(l * TT));
    }
    fc_kernel<<<BB, 256>>>(fc_w, fc_b, out);
}

// round 10
// speedup vs baseline: 1.6695x; 1.6695x over previous
#include <cuda_runtime.h>
#include <cuda_bf16.h>
#include <cstdint>
#include <cstddef>

// Problem constants
#define BB   64
#define TT   256
#define DIN  256
#define HH   1024
#define G4   4096
#define NCTA 128

// persist smem layout (bf16 elems)
#define WS2  1032            // weight row stride (1024 + 8)
#define AS3  520             // h chunk row stride (512 + 8)
#define PERSIST_SMEM (64*WS2*2 + 2*32*AS3*2 + 32*66*4)  // 132096+66560+8448 = 207104

// proj smem layout
#define PS    40             // row stride elems (32 + 8)
#define PTILE (128*PS)       // elems per stage per operand
#define PROJ_SMEM (3*PTILE*2*2 + 512)

// flag padding: 64 u32 = 256B per flag -> distinct L2 slices
#define FPAD 64

// ---------------------------------------------------------------------------
// Scratch (allocation-free: __device__ globals)
// ---------------------------------------------------------------------------
__device__ __align__(128) float          g_xg[(size_t)BB * TT * G4];
__device__ __align__(128) __nv_bfloat16  g_hs_a[(size_t)BB * TT * HH];
__device__ __align__(128) __nv_bfloat16  g_hs_b[(size_t)BB * TT * HH];
__device__ __align__(128) __nv_bfloat16  g_hbuf[2][BB * HH];
__device__ __align__(128) __nv_bfloat16  g_xb[(size_t)BB * TT * DIN];
__device__ __align__(128) __nv_bfloat16  g_wb[(size_t)(G4 * DIN + 2 * G4 * HH)];
__device__ __align__(128) unsigned       g_flags[NCTA * FPAD];

// ---------------------------------------------------------------------------
// helpers
// ---------------------------------------------------------------------------
__device__ __forceinline__ uint32_t packbf(float lo, float hi) {
    uint32_t r;
    asm("cvt.rn.bf16x2.f32 %0, %1, %2;" : "=r"(r) : "f"(hi), "f"(lo));
    return r;
}

__device__ __forceinline__ void mma_bf16(float c[4], const uint32_t a[4],
                                         uint32_t b0, uint32_t b1) {
    asm volatile(
        "mma.sync.aligned.m16n8k16.row.col.f32.bf16.bf16.f32 "
        "{%0,%1,%2,%3}, {%4,%5,%6,%7}, {%8,%9}, {%0,%1,%2,%3};\n"
        : "+f"(c[0]), "+f"(c[1]), "+f"(c[2]), "+f"(c[3])
        : "r"(a[0]), "r"(a[1]), "r"(a[2]), "r"(a[3]), "r"(b0), "r"(b1));
}

__device__ __forceinline__ uint32_t smem_u32(const void* p) {
    return (uint32_t)__cvta_generic_to_shared(p);
}

__device__ __forceinline__ void ldsm4(uint32_t r[4], uint32_t addr) {
    asm volatile("ldmatrix.sync.aligned.m8n8.x4.shared.b16 {%0,%1,%2,%3}, [%4];\n"
                 : "=r"(r[0]), "=r"(r[1]), "=r"(r[2]), "=r"(r[3]) : "r"(addr));
}

__device__ __forceinline__ void cp16(uint32_t daddr, const void* src) {
    asm volatile("cp.async.cg.shared.global [%0], [%1], 16;\n"
                 :: "r"(daddr), "l"(src));
}
#define CP_COMMIT() asm volatile("cp.async.commit_group;\n")
template <int N> __device__ __forceinline__ void cp_wait() {
    asm volatile("cp.async.wait_group %0;\n" :: "n"(N));
}

__device__ __forceinline__ unsigned ld_acq(const unsigned* p) {
    unsigned v;
    asm volatile("ld.acquire.gpu.u32 %0, [%1];" : "=r"(v) : "l"(p));
    return v;
}
__device__ __forceinline__ void st_rel(unsigned* p, unsigned v) {
    asm volatile("st.release.gpu.u32 [%0], %1;" :: "l"(p), "r"(v));
}

__device__ __forceinline__ float sigf(float x) { return 1.0f / (1.0f + __expf(-x)); }

// ---------------------------------------------------------------------------
// Convert stage A: x -> bf16
// ---------------------------------------------------------------------------
__global__ void convA_kernel(const float* __restrict__ x)
{
    int i = blockIdx.x * blockDim.x + threadIdx.x;
    if (i >= (BB * TT * DIN) / 4) return;
    float4 v = ((const float4*)x)[i];
    uint32_t* d = (uint32_t*)g_xb + (size_t)i * 2;
    d[0] = packbf(v.x, v.y);
    d[1] = packbf(v.z, v.w);
}

// ---------------------------------------------------------------------------
// Convert stage B: w_ih0/1/2 -> bf16, and zero the sync flags (per launch)
// ---------------------------------------------------------------------------
__global__ void convB_kernel(const float* __restrict__ w0,
                             const float* __restrict__ w1,
                             const float* __restrict__ w2)
{
    int i = blockIdx.x * blockDim.x + threadIdx.x;
    if (i < NCTA * FPAD) g_flags[i] = 0;
    if (i < (G4 * DIN) / 4) {
        float4 v = ((const float4*)w0)[i];
        uint32_t* d = (uint32_t*)g_wb + (size_t)i * 2;
        d[0] = packbf(v.x, v.y);
        d[1] = packbf(v.z, v.w);
    }
    if (i < (G4 * HH) / 4) {
        float4 v = ((const float4*)w1)[i];
        uint32_t* d = (uint32_t*)(g_wb + (size_t)G4 * DIN) + (size_t)i * 2;
        d[0] = packbf(v.x, v.y);
        d[1] = packbf(v.z, v.w);
        float4 u = ((const float4*)w2)[i];
        uint32_t* e = (uint32_t*)(g_wb + (size_t)G4 * (DIN + HH)) + (size_t)i * 2;
        e[0] = packbf(u.x, u.y);
        e[1] = packbf(u.z, u.w);
    }
}

// ---------------------------------------------------------------------------
// Persistent recurrent kernel: 128 CTAs = 2 batch-halves x 64 unit-groups.
// CTA (bh, ug): batches bh*32..+31, hidden units ug*16..+15 (64 gate cols).
// 256 threads, 8 warps (2M x 4N), R8-proven fragment layout.
// Weights [64][1024] bf16 stationary in SMEM; h via cp.async (2 k512 chunks).
// Monotonic padded flags; release-store ordering (no explicit fence).
// t=0 skips wait/load/GEMM (h0 == 0).
// ---------------------------------------------------------------------------
__global__ void __launch_bounds__(256, 1)
persist_kernel(const float* __restrict__ Whh, int hs_sel, unsigned base)
{
    extern __shared__ __align__(16) unsigned char smem[];
    __nv_bfloat16* Wsm = (__nv_bfloat16*)smem;            // [64][WS2]
    __nv_bfloat16* Asm = Wsm + 64 * WS2;                  // [2][32][AS3]
    float*         Gsm = (float*)(Asm + 2 * 32 * AS3);    // [32][66]

    const int tid  = threadIdx.x;
    const int cta  = blockIdx.x;
    const int bh   = cta >> 6;
    const int ug   = cta & 63;
    const int j0   = ug * 16;
    const int b0   = bh * 32;
    const int warp = tid >> 5, lane = tid & 31;
    const int g    = lane >> 2, tq = lane & 3;
    const int wm   = (warp >> 2) * 16;    // 0 / 16
    const int wn   = (warp & 3) * 16;     // 0 / 16 / 32 / 48
    const int lrow = lane & 15;
    const int lhi  = (lane >> 4) * 8;

    // pointwise mapping: 2 adjacent units per thread
    const int pb = tid >> 3;              // batch 0..31
    const int pu = (tid & 7) * 2;         // unit pair 0,2,..,14

    const unsigned* poll_p = &g_flags[(bh * 64 + (tid & 63)) * FPAD];
    unsigned* my_flag = &g_flags[(bh * 64 + ug) * FPAD];

    // ---- gather + convert weights (once per layer) ----
    for (int idx = tid; idx < 64 * 256; idx += 256) {
        int n = idx >> 8;  int k4 = (idx & 255) * 4;
        int gate = n >> 4, u = n & 15;
        float4 w = *(const float4*)(Whh + (size_t)(gate * HH + j0 + u) * HH + k4);
        uint32_t* dst = (uint32_t*)(Wsm + n * WS2 + k4);
        dst[0] = packbf(w.x, w.y);
        dst[1] = packbf(w.z, w.w);
    }
    __syncthreads();

    float cst[2] = {0.0f, 0.0f};

    for (int t = 0; t < TT; t++) {
        const __nv_bfloat16* __restrict__ hin  = g_hbuf[t & 1];
        __nv_bfloat16* __restrict__       hout = g_hbuf[(t + 1) & 1];

        // xg prefetch (float2 per gate; DRAM latency hidden behind wait/GEMM)
        float2 xv[4];
        {
            const float* xp = g_xg + ((size_t)(b0 + pb) * TT + t) * G4 + j0 + pu;
            xv[0] = *(const float2*)(xp);
            xv[1] = *(const float2*)(xp + HH);
            xv[2] = *(const float2*)(xp + 2 * HH);
            xv[3] = *(const float2*)(xp + 3 * HH);
        }

        float acc[2][4];
#pragma unroll
        for (int ns = 0; ns < 2; ns++)
#pragma unroll
            for (int q = 0; q < 4; q++) acc[ns][q] = 0.0f;

        if (t > 0) {
            // wait for all producers of this batch half (padded flags)
            if (tid < 64) {
                while ((int)ld_acq(poll_p) < (int)(base + t)) {}
            }
            __syncthreads();

            // issue both h-chunk loads (k512 each, one cp group per chunk)
#pragma unroll
            for (int kc = 0; kc < 2; kc++) {
#pragma unroll
                for (int r = 0; r < 8; r++) {
                    int lin = tid + r * 256;
                    int row = lin >> 6, c8 = (lin & 63) * 8;
                    cp16(smem_u32(Asm + kc * (32 * AS3) + row * AS3 + c8),
                         hin + (size_t)(b0 + row) * HH + kc * 512 + c8);
                }
                CP_COMMIT();
            }

            auto compute = [&](int kc) {
                const __nv_bfloat16* Ab = Asm + kc * (32 * AS3);
                const __nv_bfloat16* Wb = Wsm + kc * 512;
#pragma unroll
                for (int qp = 0; qp < 32; qp++) {
                    uint32_t af[4], bf4[4];
                    ldsm4(af, smem_u32(Ab + (wm + lrow) * AS3 + qp * 16 + lhi));
                    ldsm4(bf4, smem_u32(Wb + (wn + lrow) * WS2 + qp * 16 + lhi));
                    mma_bf16(acc[0], af, bf4[0], bf4[2]);
                    mma_bf16(acc[1], af, bf4[1], bf4[3]);
                }
            };

            cp_wait<1>(); __syncthreads(); compute(0);
            cp_wait<0>(); __syncthreads(); compute(1);
        }

        // gate exchange through SMEM
#pragma unroll
        for (int ns = 0; ns < 2; ns++) {
            int col = wn + ns * 8 + 2 * tq;
            int row = wm + g;
            Gsm[row * 66 + col]           = acc[ns][0];
            Gsm[row * 66 + col + 1]       = acc[ns][1];
            Gsm[(row + 8) * 66 + col]     = acc[ns][2];
            Gsm[(row + 8) * 66 + col + 1] = acc[ns][3];
        }
        __syncthreads();

        // pointwise LSTM update: 2 adjacent units (pb, j0+pu / j0+pu+1)
        uint32_t hpack;
        {
            float i0 = Gsm[pb * 66 + pu]          + xv[0].x;
            float i1 = Gsm[pb * 66 + pu + 1]      + xv[0].y;
            float f0 = Gsm[pb * 66 + 16 + pu]     + xv[1].x;
            float f1 = Gsm[pb * 66 + 16 + pu + 1] + xv[1].y;
            float g0 = Gsm[pb * 66 + 32 + pu]     + xv[2].x;
            float g1 = Gsm[pb * 66 + 32 + pu + 1] + xv[2].y;
            float o0 = Gsm[pb * 66 + 48 + pu]     + xv[3].x;
            float o1 = Gsm[pb * 66 + 48 + pu + 1] + xv[3].y;

            float c0 = sigf(f0) * cst[0] + sigf(i0) * tanhf(g0);
            float c1 = sigf(f1) * cst[1] + sigf(i1) * tanhf(g1);
            float h0 = sigf(o0) * tanhf(c0);
            float h1 = sigf(o1) * tanhf(c1);
            cst[0] = c0; cst[1] = c1;

            hpack = packbf(h0, h1);
            *(uint32_t*)(hout + (size_t)(b0 + pb) * HH + j0 + pu) = hpack;
        }
        __syncthreads();

        // release: bar.sync (CTA acq/rel) -> st.release.gpu gives cumulative
        // happens-before to consumers' ld.acquire — no MEMBAR.GPU needed.
        if (tid == 0) {
            st_rel(my_flag, base + (unsigned)t + 1);
        }

        // hidden-sequence store off the critical path (after flag release)
        if (hs_sel) {
            __nv_bfloat16* __restrict__ hs = (hs_sel == 1) ? g_hs_a : g_hs_b;
            *(uint32_t*)(hs + ((size_t)(b0 + pb) * TT + t) * HH + j0 + pu) = hpack;
        }
    }
}

// ---------------------------------------------------------------------------
// Projection GEMM (all-bf16, cp.async 3-stage, ldmatrix, 128x128 tile):
// g_xg[M,4096] = A[M,K] @ W[4096,K]^T + b1 + b2,  M = B*T = 16384
// ---------------------------------------------------------------------------
__global__ void __launch_bounds__(256, 2)
proj_kernel(int a_sel, size_t w_off, const float* __restrict__ b1v,
            const float* __restrict__ b2v, int K)
{
    extern __shared__ __align__(16) unsigned char smem[];
    __nv_bfloat16* Asb = (__nv_bfloat16*)smem;    // [3][128][PS]
    __nv_bfloat16* Bsb = Asb + 3 * PTILE;         // [3][128][PS]
    float*         bsm = (float*)(Bsb + 3 * PTILE);

    const __nv_bfloat16* __restrict__ A =
        (a_sel == 0) ? g_xb : (a_sel == 1 ? g_hs_a : g_hs_b);
    const __nv_bfloat16* __restrict__ W = g_wb + w_off;

    const int tid  = threadIdx.x;
    const int m0   = blockIdx.y * 128;
    const int n0   = blockIdx.x * 128;
    const int warp = tid >> 5, lane = tid & 31;
    const int g    = lane >> 2, tq = lane & 3;
    const int wmw  = (warp >> 1) * 32;    // 0/32/64/96
    const int wnw  = (warp & 1) * 64;     // 0/64
    const int lrow = lane & 15;
    const int lhi  = (lane >> 4) * 8;

    if (tid < 128) bsm[tid] = b1v[n0 + tid] + b2v[n0 + tid];

    float acc[2][8][4];
#pragma unroll
    for (int i = 0; i < 2; i++)
#pragma unroll
        for (int j = 0; j < 8; j++)
#pragma unroll
            for (int q = 0; q < 4; q++) acc[i][j][q] = 0.0f;

    auto load = [&](int kc, int st) {
#pragma unroll
        for (int r = 0; r < 2; r++) {
            int lin = tid + r * 256;
            int row = lin >> 2, c8 = (lin & 3) * 8;
            cp16(smem_u32(Asb + st * PTILE + row * PS + c8),
                 A + (size_t)(m0 + row) * K + kc * 32 + c8);
            cp16(smem_u32(Bsb + st * PTILE + row * PS + c8),
                 W + (size_t)(n0 + row) * K + kc * 32 + c8);
        }
    };

    auto compute = [&](int st) {
        const __nv_bfloat16* Ab = Asb + st * PTILE;
        const __nv_bfloat16* Bb = Bsb + st * PTILE;
#pragma unroll
        for (int q = 0; q < 2; q++) {
            uint32_t af[2][4], bf4[4][4];
            ldsm4(af[0], smem_u32(Ab + (wmw + lrow) * PS + q * 16 + lhi));
            ldsm4(af[1], smem_u32(Ab + (wmw + 16 + lrow) * PS + q * 16 + lhi));
#pragma unroll
            for (int jn = 0; jn < 4; jn++)
                ldsm4(bf4[jn], smem_u32(Bb + (wnw + jn * 16 + lrow) * PS + q * 16 + lhi));
#pragma unroll
            for (int i = 0; i < 2; i++)
#pragma unroll
                for (int j8 = 0; j8 < 8; j8++)
                    mma_bf16(acc[i][j8], af[i],
                             bf4[j8 >> 1][j8 & 1], bf4[j8 >> 1][(j8 & 1) + 2]);
        }
    };

    const int nk = K / 32;
    load(0, 0); CP_COMMIT();
    load(1, 1); CP_COMMIT();
#pragma unroll 1
    for (int kc = 0; kc < nk; kc++) {
        cp_wait<1>();
        __syncthreads();
        if (kc + 2 < nk) load(kc + 2, (kc + 2) % 3);
        CP_COMMIT();
        compute(kc % 3);
    }

    // epilogue: add biases, store fp32 to g_xg
#pragma unroll
    for (int i = 0; i < 2; i++)
#pragma unroll
        for (int j8 = 0; j8 < 8; j8++) {
            int row  = m0 + wmw + i * 16 + g;
            int lcol = wnw + j8 * 8 + 2 * tq;
            int col  = n0 + lcol;
            float bb0 = bsm[lcol], bb1 = bsm[lcol + 1];
            g_xg[(size_t)row * G4 + col]           = acc[i][j8][0] + bb0;
            g_xg[(size_t)row * G4 + col + 1]       = acc[i][j8][1] + bb1;
            g_xg[(size_t)(row + 8) * G4 + col]     = acc[i][j8][2] + bb0;
            g_xg[(size_t)(row + 8) * G4 + col + 1] = acc[i][j8][3] + bb1;
        }
}

// ---------------------------------------------------------------------------
// Final FC: out[b] = dot(h_final[b,:], fc_w) + fc_b[0];  h_final = g_hbuf[0]
// ---------------------------------------------------------------------------
__global__ void fc_kernel(const float* __restrict__ fw,
                          const float* __restrict__ fb,
                          float* __restrict__ out)
{
    __shared__ float red[8];
    int b   = blockIdx.x;
    int tid = threadIdx.x;
    const __nv_bfloat16* __restrict__ hr = g_hbuf[0] + b * HH;

    float s = 0.0f;
    for (int j = tid; j < HH; j += blockDim.x)
        s += __bfloat162float(hr[j]) * fw[j];

#pragma unroll
    for (int o = 16; o > 0; o >>= 1) s += __shfl_down_sync(0xffffffffu, s, o);
    if ((tid & 31) == 0) red[tid >> 5] = s;
    __syncthreads();
    if (tid == 0) {
        float tot = 0.0f;
        for (int w = 0; w < 8; w++) tot += red[w];
        out[b] = tot + fb[0];
    }
}

// ---------------------------------------------------------------------------
// Launch sequence (graph-capturable, kernels only):
// convA, convB, (proj, persist) x3, fc
// ---------------------------------------------------------------------------
extern "C" void kernel_launch(void* const* d_in, const int* in_sizes, int n_in,
                              void* d_out, int out_size)
{
    const float* x       = (const float*)d_in[0];
    const float* w_ih[3] = { (const float*)d_in[1], (const float*)d_in[5], (const float*)d_in[9]  };
    const float* w_hh[3] = { (const float*)d_in[2], (const float*)d_in[6], (const float*)d_in[10] };
    const float* b_ih[3] = { (const float*)d_in[3], (const float*)d_in[7], (const float*)d_in[11] };
    const float* b_hh[3] = { (const float*)d_in[4], (const float*)d_in[8], (const float*)d_in[12] };
    const float* fc_w    = (const float*)d_in[13];
    const float* fc_b    = (const float*)d_in[14];
    float* out = (float*)d_out;

    cudaFuncSetAttribute(persist_kernel,
                         cudaFuncAttributeMaxDynamicSharedMemorySize, PERSIST_SMEM);
    cudaFuncSetAttribute(proj_kernel,
                         cudaFuncAttributeMaxDynamicSharedMemorySize, PROJ_SMEM);

    convA_kernel<<<(BB * TT * DIN / 4 + 255) / 256, 256>>>(x);
    convB_kernel<<<(G4 * HH / 4 + 255) / 256, 256>>>(w_ih[0], w_ih[1], w_ih[2]);

    const int    a_sel[3]  = { 0, 1, 2 };
    const int    hs_sel[3] = { 1, 2, 0 };
    const int    K_in[3]   = { DIN, HH, HH };
    const size_t w_off[3]  = { 0, (size_t)G4 * DIN, (size_t)G4 * (DIN + HH) };

    dim3 pgrid(32, 128);

    for (int l = 0; l < 3; l++) {
        proj_kernel<<<pgrid, 256, PROJ_SMEM>>>(a_sel[l], w_off[l], b_ih[l], b_hh[l], K_in[l]);
        persist_kernel<<<NCTA, 256, PERSIST_SMEM>>>(w_hh[l], hs_sel[l],
                                                    (unsigned)(l * TT));
    }
    fc_kernel<<<BB, 256>>>(fc_w, fc_b, out);
}

// round 12
// speedup vs baseline: 1.6699x; 1.0003x over previous
#include <cuda_runtime.h>
#include <cuda_bf16.h>
#include <cstdint>
#include <cstddef>

// Problem constants
#define BB   64
#define TT   256
#define DIN  256
#define HH   1024
#define G4   4096
#define NCTA 128

// persist smem layout (bf16 elems)
#define WS2  1032            // weight row stride (1024 + 8)
#define ASC  264             // h chunk row stride (256 + 8)
#define PERSIST_SMEM (64*WS2*2 + 4*32*ASC*2 + 32*66*4)  // 132096+67584+8448 = 208128

// proj smem layout
#define PS    40             // row stride elems (32 + 8)
#define PTILE (128*PS)       // elems per stage per operand
#define PROJ_SMEM (3*PTILE*2*2 + 512)

// flag padding: 64 u32 = 256B per flag -> distinct L2 slices
#define FPAD 64

// ---------------------------------------------------------------------------
// Scratch (allocation-free: __device__ globals)
// ---------------------------------------------------------------------------
__device__ __align__(128) float          g_xg[(size_t)BB * TT * G4];
__device__ __align__(128) __nv_bfloat16  g_hs_a[(size_t)BB * TT * HH];
__device__ __align__(128) __nv_bfloat16  g_hs_b[(size_t)BB * TT * HH];
__device__ __align__(128) __nv_bfloat16  g_hbuf[2][BB * HH];
__device__ __align__(128) __nv_bfloat16  g_xb[(size_t)BB * TT * DIN];
__device__ __align__(128) __nv_bfloat16  g_wb[(size_t)(G4 * DIN + 2 * G4 * HH)];
__device__ __align__(128) unsigned       g_flags[NCTA * FPAD];

// ---------------------------------------------------------------------------
// helpers
// ---------------------------------------------------------------------------
__device__ __forceinline__ uint32_t packbf(float lo, float hi) {
    uint32_t r;
    asm("cvt.rn.bf16x2.f32 %0, %1, %2;" : "=r"(r) : "f"(hi), "f"(lo));
    return r;
}

__device__ __forceinline__ void mma_bf16(float c[4], const uint32_t a[4],
                                         uint32_t b0, uint32_t b1) {
    asm volatile(
        "mma.sync.aligned.m16n8k16.row.col.f32.bf16.bf16.f32 "
        "{%0,%1,%2,%3}, {%4,%5,%6,%7}, {%8,%9}, {%0,%1,%2,%3};\n"
        : "+f"(c[0]), "+f"(c[1]), "+f"(c[2]), "+f"(c[3])
        : "r"(a[0]), "r"(a[1]), "r"(a[2]), "r"(a[3]), "r"(b0), "r"(b1));
}

__device__ __forceinline__ uint32_t smem_u32(const void* p) {
    return (uint32_t)__cvta_generic_to_shared(p);
}

__device__ __forceinline__ void ldsm4(uint32_t r[4], uint32_t addr) {
    asm volatile("ldmatrix.sync.aligned.m8n8.x4.shared.b16 {%0,%1,%2,%3}, [%4];\n"
                 : "=r"(r[0]), "=r"(r[1]), "=r"(r[2]), "=r"(r[3]) : "r"(addr));
}

__device__ __forceinline__ void cp16(uint32_t daddr, const void* src) {
    asm volatile("cp.async.cg.shared.global [%0], [%1], 16;\n"
                 :: "r"(daddr), "l"(src));
}
#define CP_COMMIT() asm volatile("cp.async.commit_group;\n")
template <int N> __device__ __forceinline__ void cp_wait() {
    asm volatile("cp.async.wait_group %0;\n" :: "n"(N));
}

__device__ __forceinline__ unsigned ld_acq(const unsigned* p) {
    unsigned v;
    asm volatile("ld.acquire.gpu.u32 %0, [%1];" : "=r"(v) : "l"(p));
    return v;
}
__device__ __forceinline__ void st_rel(unsigned* p, unsigned v) {
    asm volatile("st.release.gpu.u32 [%0], %1;" :: "l"(p), "r"(v));
}

__device__ __forceinline__ float sigf(float x) { return 1.0f / (1.0f + __expf(-x)); }

// ---------------------------------------------------------------------------
// Convert stage A: x -> bf16
// ---------------------------------------------------------------------------
__global__ void convA_kernel(const float* __restrict__ x)
{
    int i = blockIdx.x * blockDim.x + threadIdx.x;
    if (i >= (BB * TT * DIN) / 4) return;
    float4 v = ((const float4*)x)[i];
    uint32_t* d = (uint32_t*)g_xb + (size_t)i * 2;
    d[0] = packbf(v.x, v.y);
    d[1] = packbf(v.z, v.w);
}

// ---------------------------------------------------------------------------
// Convert stage B: w_ih0/1/2 -> bf16, and zero the sync flags (per launch)
// ---------------------------------------------------------------------------
__global__ void convB_kernel(const float* __restrict__ w0,
                             const float* __restrict__ w1,
                             const float* __restrict__ w2)
{
    int i = blockIdx.x * blockDim.x + threadIdx.x;
    if (i < NCTA * FPAD) g_flags[i] = 0;
    if (i < (G4 * DIN) / 4) {
        float4 v = ((const float4*)w0)[i];
        uint32_t* d = (uint32_t*)g_wb + (size_t)i * 2;
        d[0] = packbf(v.x, v.y);
        d[1] = packbf(v.z, v.w);
    }
    if (i < (G4 * HH) / 4) {
        float4 v = ((const float4*)w1)[i];
        uint32_t* d = (uint32_t*)(g_wb + (size_t)G4 * DIN) + (size_t)i * 2;
        d[0] = packbf(v.x, v.y);
        d[1] = packbf(v.z, v.w);
        float4 u = ((const float4*)w2)[i];
        uint32_t* e = (uint32_t*)(g_wb + (size_t)G4 * (DIN + HH)) + (size_t)i * 2;
        e[0] = packbf(u.x, u.y);
        e[1] = packbf(u.z, u.w);
    }
}

// ---------------------------------------------------------------------------
// Persistent recurrent kernel: 128 CTAs = 2 batch-halves x 64 unit-groups.
// CTA (bh, ug): batches bh*32..+31, hidden units ug*16..+15 (64 gate cols).
// 256 threads, 8 warps (2M x 4N). Weights [64][1024] bf16 stationary in SMEM.
// h via cp.async in 4 k256 chunks, each gated on ONLY its 16 producer flags,
// processed in rotated order (start = ug & 3) so producer-tail and load
// latency hide behind compute of earlier chunks.
// Monotonic padded flags; release-store ordering. t=0 skips wait/load/GEMM.
// ---------------------------------------------------------------------------
__global__ void __launch_bounds__(256, 1)
persist_kernel(const float* __restrict__ Whh, int hs_sel, unsigned base)
{
    extern __shared__ __align__(16) unsigned char smem[];
    __nv_bfloat16* Wsm = (__nv_bfloat16*)smem;            // [64][WS2]
    __nv_bfloat16* Asm = Wsm + 64 * WS2;                  // [4][32][ASC]
    float*         Gsm = (float*)(Asm + 4 * 32 * ASC);    // [32][66]

    const int tid  = threadIdx.x;
    const int cta  = blockIdx.x;
    const int bh   = cta >> 6;
    const int ug   = cta & 63;
    const int j0   = ug * 16;
    const int b0   = bh * 32;
    const int warp = tid >> 5, lane = tid & 31;
    const int g    = lane >> 2, tq = lane & 3;
    const int wm   = (warp >> 2) * 16;    // 0 / 16
    const int wn   = (warp & 3) * 16;     // 0 / 16 / 32 / 48
    const int lrow = lane & 15;
    const int lhi  = (lane >> 4) * 8;

    // pointwise mapping: 2 adjacent units per thread
    const int pb = tid >> 3;              // batch 0..31
    const int pu = (tid & 7) * 2;         // unit pair 0,2,..,14

    // chunk loader identity: this thread's bytes belong to producer sub
    const int sub = (tid & 31) >> 1;      // producer index within chunk (0..15)
    unsigned* my_flag = &g_flags[(bh * 64 + ug) * FPAD];

    // ---- gather + convert weights (once per layer) ----
    for (int idx = tid; idx < 64 * 256; idx += 256) {
        int n = idx >> 8;  int k4 = (idx & 255) * 4;
        int gate = n >> 4, u = n & 15;
        float4 w = *(const float4*)(Whh + (size_t)(gate * HH + j0 + u) * HH + k4);
        uint32_t* dst = (uint32_t*)(Wsm + n * WS2 + k4);
        dst[0] = packbf(w.x, w.y);
        dst[1] = packbf(w.z, w.w);
    }
    __syncthreads();

    float cst[2] = {0.0f, 0.0f};
    const int rot = ug & 3;

    for (int t = 0; t < TT; t++) {
        const __nv_bfloat16* __restrict__ hin  = g_hbuf[t & 1];
        __nv_bfloat16* __restrict__       hout = g_hbuf[(t + 1) & 1];

        // xg prefetch (float2 per gate; DRAM latency hidden behind wait/GEMM)
        float2 xv[4];
        {
            const float* xp = g_xg + ((size_t)(b0 + pb) * TT + t) * G4 + j0 + pu;
            xv[0] = *(const float2*)(xp);
            xv[1] = *(const float2*)(xp + HH);
            xv[2] = *(const float2*)(xp + 2 * HH);
            xv[3] = *(const float2*)(xp + 3 * HH);
        }

        float acc[2][4];
#pragma unroll
        for (int ns = 0; ns < 2; ns++)
#pragma unroll
            for (int q = 0; q < 4; q++) acc[ns][q] = 0.0f;

        if (t > 0) {
            // gate + load one k256 chunk: poll only its 16 producer flags,
            // then issue 32 rows x 512B of cp.async (one commit group)
            auto gate_load = [&](int kc) {
                const unsigned* fp =
                    &g_flags[(bh * 64 + kc * 16 + sub) * FPAD];
                while ((int)ld_acq(fp) < (int)(base + t)) {}
#pragma unroll
                for (int r = 0; r < 4; r++) {
                    int lin = tid + r * 256;
                    int row = lin >> 5, c8 = (lin & 31) * 8;
                    cp16(smem_u32(Asm + kc * (32 * ASC) + row * ASC + c8),
                         hin + (size_t)(b0 + row) * HH + kc * 256 + c8);
                }
                CP_COMMIT();
            };

            auto compute = [&](int kc) {
                const __nv_bfloat16* Ab = Asm + kc * (32 * ASC);
                const __nv_bfloat16* Wb = Wsm + kc * 256;
#pragma unroll
                for (int qp = 0; qp < 16; qp++) {
                    uint32_t af[4], bf4[4];
                    ldsm4(af, smem_u32(Ab + (wm + lrow) * ASC + qp * 16 + lhi));
                    ldsm4(bf4, smem_u32(Wb + (wn + lrow) * WS2 + qp * 16 + lhi));
                    mma_bf16(acc[0], af, bf4[0], bf4[2]);
                    mma_bf16(acc[1], af, bf4[1], bf4[3]);
                }
            };

            const int c0 = rot, c1 = (rot + 1) & 3,
                      c2 = (rot + 2) & 3, c3 = (rot + 3) & 3;

            gate_load(c0);
            gate_load(c1);
            cp_wait<1>(); __syncthreads(); compute(c0);
            gate_load(c2);
            cp_wait<1>(); __syncthreads(); compute(c1);
            gate_load(c3);
            cp_wait<1>(); __syncthreads(); compute(c2);
            cp_wait<0>(); __syncthreads(); compute(c3);
        }

        // gate exchange through SMEM
#pragma unroll
        for (int ns = 0; ns < 2; ns++) {
            int col = wn + ns * 8 + 2 * tq;
            int row = wm + g;
            Gsm[row * 66 + col]           = acc[ns][0];
            Gsm[row * 66 + col + 1]       = acc[ns][1];
            Gsm[(row + 8) * 66 + col]     = acc[ns][2];
            Gsm[(row + 8) * 66 + col + 1] = acc[ns][3];
        }
        __syncthreads();

        // pointwise LSTM update: 2 adjacent units (pb, j0+pu / j0+pu+1)
        uint32_t hpack;
        {
            float i0 = Gsm[pb * 66 + pu]          + xv[0].x;
            float i1 = Gsm[pb * 66 + pu + 1]      + xv[0].y;
            float f0 = Gsm[pb * 66 + 16 + pu]     + xv[1].x;
            float f1 = Gsm[pb * 66 + 16 + pu + 1] + xv[1].y;
            float g0 = Gsm[pb * 66 + 32 + pu]     + xv[2].x;
            float g1 = Gsm[pb * 66 + 32 + pu + 1] + xv[2].y;
            float o0 = Gsm[pb * 66 + 48 + pu]     + xv[3].x;
            float o1 = Gsm[pb * 66 + 48 + pu + 1] + xv[3].y;

            float c0 = sigf(f0) * cst[0] + sigf(i0) * tanhf(g0);
            float c1 = sigf(f1) * cst[1] + sigf(i1) * tanhf(g1);
            float h0 = sigf(o0) * tanhf(c0);
            float h1 = sigf(o1) * tanhf(c1);
            cst[0] = c0; cst[1] = c1;

            hpack = packbf(h0, h1);
            *(uint32_t*)(hout + (size_t)(b0 + pb) * HH + j0 + pu) = hpack;
        }
        __syncthreads();

        // release: bar.sync (CTA acq/rel) -> st.release.gpu gives cumulative
        // happens-before to consumers' ld.acquire — no MEMBAR.GPU needed.
        if (tid == 0) {
            st_rel(my_flag, base + (unsigned)t + 1);
        }

        // hidden-sequence store off the critical path (after flag release)
        if (hs_sel) {
            __nv_bfloat16* __restrict__ hs = (hs_sel == 1) ? g_hs_a : g_hs_b;
            *(uint32_t*)(hs + ((size_t)(b0 + pb) * TT + t) * HH + j0 + pu) = hpack;
        }
    }
}

// ---------------------------------------------------------------------------
// Projection GEMM (all-bf16, cp.async 3-stage, ldmatrix, 128x128 tile):
// g_xg[M,4096] = A[M,K] @ W[4096,K]^T + b1 + b2,  M = B*T = 16384
// ---------------------------------------------------------------------------
__global__ void __launch_bounds__(256, 2)
proj_kernel(int a_sel, size_t w_off, const float* __restrict__ b1v,
            const float* __restrict__ b2v, int K)
{
    extern __shared__ __align__(16) unsigned char smem[];
    __nv_bfloat16* Asb = (__nv_bfloat16*)smem;    // [3][128][PS]
    __nv_bfloat16* Bsb = Asb + 3 * PTILE;         // [3][128][PS]
    float*         bsm = (float*)(Bsb + 3 * PTILE);

    const __nv_bfloat16* __restrict__ A =
        (a_sel == 0) ? g_xb : (a_sel == 1 ? g_hs_a : g_hs_b);
    const __nv_bfloat16* __restrict__ W = g_wb + w_off;

    const int tid  = threadIdx.x;
    const int m0   = blockIdx.y * 128;
    const int n0   = blockIdx.x * 128;
    const int warp = tid >> 5, lane = tid & 31;
    const int g    = lane >> 2, tq = lane & 3;
    const int wmw  = (warp >> 1) * 32;    // 0/32/64/96
    const int wnw  = (warp & 1) * 64;     // 0/64
    const int lrow = lane & 15;
    const int lhi  = (lane >> 4) * 8;

    if (tid < 128) bsm[tid] = b1v[n0 + tid] + b2v[n0 + tid];

    float acc[2][8][4];
#pragma unroll
    for (int i = 0; i < 2; i++)
#pragma unroll
        for (int j = 0; j < 8; j++)
#pragma unroll
            for (int q = 0; q < 4; q++) acc[i][j][q] = 0.0f;

    auto load = [&](int kc, int st) {
#pragma unroll
        for (int r = 0; r < 2; r++) {
            int lin = tid + r * 256;
            int row = lin >> 2, c8 = (lin & 3) * 8;
            cp16(smem_u32(Asb + st * PTILE + row * PS + c8),
                 A + (size_t)(m0 + row) * K + kc * 32 + c8);
            cp16(smem_u32(Bsb + st * PTILE + row * PS + c8),
                 W + (size_t)(n0 + row) * K + kc * 32 + c8);
        }
    };

    auto compute = [&](int st) {
        const __nv_bfloat16* Ab = Asb + st * PTILE;
        const __nv_bfloat16* Bb = Bsb + st * PTILE;
#pragma unroll
        for (int q = 0; q < 2; q++) {
            uint32_t af[2][4], bf4[4][4];
            ldsm4(af[0], smem_u32(Ab + (wmw + lrow) * PS + q * 16 + lhi));
            ldsm4(af[1], smem_u32(Ab + (wmw + 16 + lrow) * PS + q * 16 + lhi));
#pragma unroll
            for (int jn = 0; jn < 4; jn++)
                ldsm4(bf4[jn], smem_u32(Bb + (wnw + jn * 16 + lrow) * PS + q * 16 + lhi));
#pragma unroll
            for (int i = 0; i < 2; i++)
#pragma unroll
                for (int j8 = 0; j8 < 8; j8++)
                    mma_bf16(acc[i][j8], af[i],
                             bf4[j8 >> 1][j8 & 1], bf4[j8 >> 1][(j8 & 1) + 2]);
        }
    };

    const int nk = K / 32;
    load(0, 0); CP_COMMIT();
    load(1, 1); CP_COMMIT();
#pragma unroll 1
    for (int kc = 0; kc < nk; kc++) {
        cp_wait<1>();
        __syncthreads();
        if (kc + 2 < nk) load(kc + 2, (kc + 2) % 3);
        CP_COMMIT();
        compute(kc % 3);
    }

    // epilogue: add biases, store fp32 to g_xg
#pragma unroll
    for (int i = 0; i < 2; i++)
#pragma unroll
        for (int j8 = 0; j8 < 8; j8++) {
            int row  = m0 + wmw + i * 16 + g;
            int lcol = wnw + j8 * 8 + 2 * tq;
            int col  = n0 + lcol;
            float bb0 = bsm[lcol], bb1 = bsm[lcol + 1];
            g_xg[(size_t)row * G4 + col]           = acc[i][j8][0] + bb0;
            g_xg[(size_t)row * G4 + col + 1]       = acc[i][j8][1] + bb1;
            g_xg[(size_t)(row + 8) * G4 + col]     = acc[i][j8][2] + bb0;
            g_xg[(size_t)(row + 8) * G4 + col + 1] = acc[i][j8][3] + bb1;
        }
}

// ---------------------------------------------------------------------------
// Final FC: out[b] = dot(h_final[b,:], fc_w) + fc_b[0];  h_final = g_hbuf[0]
// ---------------------------------------------------------------------------
__global__ void fc_kernel(const float* __restrict__ fw,
                          const float* __restrict__ fb,
                          float* __restrict__ out)
{
    __shared__ float red[8];
    int b   = blockIdx.x;
    int tid = threadIdx.x;
    const __nv_bfloat16* __restrict__ hr = g_hbuf[0] + b * HH;

    float s = 0.0f;
    for (int j = tid; j < HH; j += blockDim.x)
        s += __bfloat162float(hr[j]) * fw[j];

#pragma unroll
    for (int o = 16; o > 0; o >>= 1) s += __shfl_down_sync(0xffffffffu, s, o);
    if ((tid & 31) == 0) red[tid >> 5] = s;
    __syncthreads();
    if (tid == 0) {
        float tot = 0.0f;
        for (int w = 0; w < 8; w++) tot += red[w];
        out[b] = tot + fb[0];
    }
}

// ---------------------------------------------------------------------------
// Launch sequence (graph-capturable, kernels only):
// convA, convB, (proj, persist) x3, fc
// ---------------------------------------------------------------------------
extern "C" void kernel_launch(void* const* d_in, const int* in_sizes, int n_in,
                              void* d_out, int out_size)
{
    const float* x       = (const float*)d_in[0];
    const float* w_ih[3] = { (const float*)d_in[1], (const float*)d_in[5], (const float*)d_in[9]  };
    const float* w_hh[3] = { (const float*)d_in[2], (const float*)d_in[6], (const float*)d_in[10] };
    const float* b_ih[3] = { (const float*)d_in[3], (const float*)d_in[7], (const float*)d_in[11] };
    const float* b_hh[3] = { (const float*)d_in[4], (const float*)d_in[8], (const float*)d_in[12] };
    const float* fc_w    = (const float*)d_in[13];
    const float* fc_b    = (const float*)d_in[14];
    float* out = (float*)d_out;

    cudaFuncSetAttribute(persist_kernel,
                         cudaFuncAttributeMaxDynamicSharedMemorySize, PERSIST_SMEM);
    cudaFuncSetAttribute(proj_kernel,
                         cudaFuncAttributeMaxDynamicSharedMemorySize, PROJ_SMEM);

    convA_kernel<<<(BB * TT * DIN / 4 + 255) / 256, 256>>>(x);
    convB_kernel<<<(G4 * HH / 4 + 255) / 256, 256>>>(w_ih[0], w_ih[1], w_ih[2]);

    const int    a_sel[3]  = { 0, 1, 2 };
    const int    hs_sel[3] = { 1, 2, 0 };
    const int    K_in[3]   = { DIN, HH, HH };
    const size_t w_off[3]  = { 0, (size_t)G4 * DIN, (size_t)G4 * (DIN + HH) };

    dim3 pgrid(32, 128);

    for (int l = 0; l < 3; l++) {
        proj_kernel<<<pgrid, 256, PROJ_SMEM>>>(a_sel[l], w_off[l], b_ih[l], b_hh[l], K_in[l]);
        persist_kernel<<<NCTA, 256, PERSIST_SMEM>>>(w_hh[l], hs_sel[l],
                                                    (unsigned)(l * TT));
    }
    fc_kernel<<<BB, 256>>>(fc_w, fc_b, out);
}

// round 13
// speedup vs baseline: 1.8420x; 1.1031x over previous
#include <cuda_runtime.h>
#include <cuda_bf16.h>
#include <cstdint>
#include <cstddef>

// Problem constants
#define BB   64
#define TT   256
#define DIN  256
#define HH   1024
#define G4   4096
#define NCTA 128

// persist smem layout
#define WS2  1032            // weight row stride elems (1024 + 8)
#define GSM_OFF  (64*WS2*2 + 32*1024*2)            // 197632
#define MBAR_OFF (GSM_OFF + 32*66*4)               // 206080
#define PERSIST_SMEM (MBAR_OFF + 16)               // 206096

// proj smem layout
#define PS    40             // row stride elems (32 + 8)
#define PTILE (128*PS)       // elems per stage per operand
#define PROJ_SMEM (3*PTILE*2*2 + 512)

// flag padding: 64 u32 = 256B per flag -> distinct L2 slices
#define FPAD 64

// ---------------------------------------------------------------------------
// Scratch (allocation-free: __device__ globals)
// ---------------------------------------------------------------------------
__device__ __align__(128) float          g_xg[(size_t)BB * TT * G4];
__device__ __align__(128) __nv_bfloat16  g_hs_a[(size_t)BB * TT * HH];
__device__ __align__(128) __nv_bfloat16  g_hs_b[(size_t)BB * TT * HH];
__device__ __align__(128) __nv_bfloat16  g_hbuf[2][BB * HH];   // SWIZZLED layout
__device__ __align__(128) __nv_bfloat16  g_xb[(size_t)BB * TT * DIN];
__device__ __align__(128) __nv_bfloat16  g_wb[(size_t)(G4 * DIN + 2 * G4 * HH)];
__device__ __align__(128) unsigned       g_flags[NCTA * FPAD];

// ---------------------------------------------------------------------------
// helpers
// ---------------------------------------------------------------------------
__device__ __forceinline__ uint32_t packbf(float lo, float hi) {
    uint32_t r;
    asm("cvt.rn.bf16x2.f32 %0, %1, %2;" : "=r"(r) : "f"(hi), "f"(lo));
    return r;
}

__device__ __forceinline__ void mma_bf16(float c[4], const uint32_t a[4],
                                         uint32_t b0, uint32_t b1) {
    asm volatile(
        "mma.sync.aligned.m16n8k16.row.col.f32.bf16.bf16.f32 "
        "{%0,%1,%2,%3}, {%4,%5,%6,%7}, {%8,%9}, {%0,%1,%2,%3};\n"
        : "+f"(c[0]), "+f"(c[1]), "+f"(c[2]), "+f"(c[3])
        : "r"(a[0]), "r"(a[1]), "r"(a[2]), "r"(a[3]), "r"(b0), "r"(b1));
}

__device__ __forceinline__ uint32_t smem_u32(const void* p) {
    return (uint32_t)__cvta_generic_to_shared(p);
}

__device__ __forceinline__ void ldsm4(uint32_t r[4], uint32_t addr) {
    asm volatile("ldmatrix.sync.aligned.m8n8.x4.shared.b16 {%0,%1,%2,%3}, [%4];\n"
                 : "=r"(r[0]), "=r"(r[1]), "=r"(r[2]), "=r"(r[3]) : "r"(addr));
}

__device__ __forceinline__ void cp16(uint32_t daddr, const void* src) {
    asm volatile("cp.async.cg.shared.global [%0], [%1], 16;\n"
                 :: "r"(daddr), "l"(src));
}
#define CP_COMMIT() asm volatile("cp.async.commit_group;\n")
template <int N> __device__ __forceinline__ void cp_wait() {
    asm volatile("cp.async.wait_group %0;\n" :: "n"(N));
}

__device__ __forceinline__ unsigned ld_acq(const unsigned* p) {
    unsigned v;
    asm volatile("ld.acquire.gpu.u32 %0, [%1];" : "=r"(v) : "l"(p));
    return v;
}
__device__ __forceinline__ void st_rel(unsigned* p, unsigned v) {
    asm volatile("st.release.gpu.u32 [%0], %1;" :: "l"(p), "r"(v));
}

__device__ __forceinline__ void mbar_wait(uint32_t mbar, uint32_t parity) {
    asm volatile(
        "{\n\t.reg .pred P;\n\t"
        "WAIT_%=:\n\t"
        "mbarrier.try_wait.parity.shared.b64 P, [%0], %1;\n\t"
        "@!P bra WAIT_%=;\n\t}"
        :: "r"(mbar), "r"(parity) : "memory");
}

__device__ __forceinline__ float sigf(float x) { return 1.0f / (1.0f + __expf(-x)); }

// ---------------------------------------------------------------------------
// Convert stage A: x -> bf16
// ---------------------------------------------------------------------------
__global__ void convA_kernel(const float* __restrict__ x)
{
    int i = blockIdx.x * blockDim.x + threadIdx.x;
    if (i >= (BB * TT * DIN) / 4) return;
    float4 v = ((const float4*)x)[i];
    uint32_t* d = (uint32_t*)g_xb + (size_t)i * 2;
    d[0] = packbf(v.x, v.y);
    d[1] = packbf(v.z, v.w);
}

// ---------------------------------------------------------------------------
// Convert stage B: w_ih0/1/2 -> bf16, and zero the sync flags (per launch)
// ---------------------------------------------------------------------------
__global__ void convB_kernel(const float* __restrict__ w0,
                             const float* __restrict__ w1,
                             const float* __restrict__ w2)
{
    int i = blockIdx.x * blockDim.x + threadIdx.x;
    if (i < NCTA * FPAD) g_flags[i] = 0;
    if (i < (G4 * DIN) / 4) {
        float4 v = ((const float4*)w0)[i];
        uint32_t* d = (uint32_t*)g_wb + (size_t)i * 2;
        d[0] = packbf(v.x, v.y);
        d[1] = packbf(v.z, v.w);
    }
    if (i < (G4 * HH) / 4) {
        float4 v = ((const float4*)w1)[i];
        uint32_t* d = (uint32_t*)(g_wb + (size_t)G4 * DIN) + (size_t)i * 2;
        d[0] = packbf(v.x, v.y);
        d[1] = packbf(v.z, v.w);
        float4 u = ((const float4*)w2)[i];
        uint32_t* e = (uint32_t*)(g_wb + (size_t)G4 * (DIN + HH)) + (size_t)i * 2;
        e[0] = packbf(u.x, u.y);
        e[1] = packbf(u.z, u.w);
    }
}

// ---------------------------------------------------------------------------
// Persistent recurrent kernel: 128 CTAs = 2 batch-halves x 64 unit-groups.
// CTA (bh, ug): batches bh*32..+31, hidden units ug*16..+15 (64 gate cols).
// 256 threads, 8 warps (2M x 4N). Weights [64][1024] bf16 stationary in SMEM.
// h tile (contiguous 64KB) arrives via 4x cp.async.bulk into ONE mbarrier —
// replaces 4096 LDGSTS/step (8 cyc/op issue floor) with 4 instructions.
// g_hbuf uses a 16B-granular XOR swizzle (col ^ ((batch&7)<<4)) written by
// the producer so the unpadded 2KB-row smem tile is LDSM-conflict-free.
// Monotonic padded flags; release-store ordering. t=0 skips wait/load/GEMM.
// ---------------------------------------------------------------------------
__global__ void __launch_bounds__(256, 1)
persist_kernel(const float* __restrict__ Whh, int hs_sel, unsigned base)
{
    extern __shared__ __align__(128) unsigned char smem[];
    __nv_bfloat16* Wsm = (__nv_bfloat16*)smem;            // [64][WS2]
    __nv_bfloat16* Asm = Wsm + 64 * WS2;                  // [32][1024] unpadded
    float*         Gsm = (float*)(smem + GSM_OFF);        // [32][66]
    const uint32_t mbar = smem_u32(smem + MBAR_OFF);
    const uint32_t Abase = smem_u32(Asm);

    const int tid  = threadIdx.x;
    const int cta  = blockIdx.x;
    const int bh   = cta >> 6;
    const int ug   = cta & 63;
    const int j0   = ug * 16;
    const int b0   = bh * 32;
    const int warp = tid >> 5, lane = tid & 31;
    const int g    = lane >> 2, tq = lane & 3;
    const int wm   = (warp >> 2) * 16;    // 0 / 16
    const int wn   = (warp & 3) * 16;     // 0 / 16 / 32 / 48
    const int lrow = lane & 15;
    const int lhi  = (lane >> 4) * 8;

    // A-side ldsm addressing (swizzled, unpadded 2048B rows)
    const int      ar  = wm + lrow;
    const uint32_t Ar  = Abase + ar * 2048;
    const uint32_t xr  = (ar & 7) << 4;
    const uint32_t lb  = lhi * 2;          // 0 or 16 bytes

    // pointwise mapping: 2 adjacent units per thread
    const int pb = tid >> 3;              // batch 0..31
    const int pu = (tid & 7) * 2;         // unit pair 0,2,..,14
    const uint32_t hswz = ((uint32_t)((j0 + pu) * 2)) ^ ((uint32_t)(pb & 7) << 4);

    const unsigned* poll_p = &g_flags[(bh * 64 + (tid & 63)) * FPAD];
    unsigned* my_flag = &g_flags[(bh * 64 + ug) * FPAD];

    // ---- init mbarrier + gather/convert weights (once per layer) ----
    if (tid == 0) {
        asm volatile("mbarrier.init.shared.b64 [%0], 1;" :: "r"(mbar) : "memory");
    }
    for (int idx = tid; idx < 64 * 256; idx += 256) {
        int n = idx >> 8;  int k4 = (idx & 255) * 4;
        int gate = n >> 4, u = n & 15;
        float4 w = *(const float4*)(Whh + (size_t)(gate * HH + j0 + u) * HH + k4);
        uint32_t* dst = (uint32_t*)(Wsm + n * WS2 + k4);
        dst[0] = packbf(w.x, w.y);
        dst[1] = packbf(w.z, w.w);
    }
    __syncthreads();

    float cst[2] = {0.0f, 0.0f};

    for (int t = 0; t < TT; t++) {
        const __nv_bfloat16* __restrict__ hin  = g_hbuf[t & 1];
        __nv_bfloat16* __restrict__       hout = g_hbuf[(t + 1) & 1];

        // xg prefetch (float2 per gate; DRAM latency hidden behind wait/GEMM)
        float2 xv[4];
        {
            const float* xp = g_xg + ((size_t)(b0 + pb) * TT + t) * G4 + j0 + pu;
            xv[0] = *(const float2*)(xp);
            xv[1] = *(const float2*)(xp + HH);
            xv[2] = *(const float2*)(xp + 2 * HH);
            xv[3] = *(const float2*)(xp + 3 * HH);
        }

        float acc[2][4];
#pragma unroll
        for (int ns = 0; ns < 2; ns++)
#pragma unroll
            for (int q = 0; q < 4; q++) acc[ns][q] = 0.0f;

        if (t > 0) {
            // wait for all 64 producers of this batch half (padded flags)
            if (tid < 64) {
                while ((int)ld_acq(poll_p) < (int)(base + t)) {}
            }
            __syncthreads();

            // one bulk-copy sequence: 64KB contiguous h tile -> Asm
            if (tid == 0) {
                asm volatile(
                    "mbarrier.arrive.expect_tx.shared.b64 _, [%0], %1;"
                    :: "r"(mbar), "r"(65536u) : "memory");
                const char* src = (const char*)hin + (size_t)b0 * 2048;
#pragma unroll
                for (int c = 0; c < 4; c++) {
                    asm volatile(
                        "cp.async.bulk.shared::cta.global.mbarrier::complete_tx::bytes "
                        "[%0], [%1], %2, [%3];"
                        :: "r"(Abase + c * 16384), "l"(src + c * 16384),
                           "r"(16384u), "r"(mbar) : "memory");
                }
            }
            mbar_wait(mbar, (unsigned)((t - 1) & 1));

            // GEMM over 4 k256 chunks (no intermediate barriers)
#pragma unroll 1
            for (int kc = 0; kc < 4; kc++) {
                const __nv_bfloat16* Wb = Wsm + kc * 256;
                const uint32_t Ak = Ar + kc * 512;
#pragma unroll
                for (int qp = 0; qp < 16; qp++) {
                    uint32_t af[4], bf4[4];
                    ldsm4(af, Ak + (((uint32_t)(qp * 32) + lb) ^ xr));
                    ldsm4(bf4, smem_u32(Wb + (wn + lrow) * WS2 + qp * 16 + lhi));
                    mma_bf16(acc[0], af, bf4[0], bf4[2]);
                    mma_bf16(acc[1], af, bf4[1], bf4[3]);
                }
            }

            // order generic LDSM reads before next step's async-proxy writes
            asm volatile("fence.proxy.async.shared::cta;" ::: "memory");
        }

        // gate exchange through SMEM
#pragma unroll
        for (int ns = 0; ns < 2; ns++) {
            int col = wn + ns * 8 + 2 * tq;
            int row = wm + g;
            Gsm[row * 66 + col]           = acc[ns][0];
            Gsm[row * 66 + col + 1]       = acc[ns][1];
            Gsm[(row + 8) * 66 + col]     = acc[ns][2];
            Gsm[(row + 8) * 66 + col + 1] = acc[ns][3];
        }
        __syncthreads();

        // pointwise LSTM update: 2 adjacent units (pb, j0+pu / j0+pu+1)
        uint32_t hpack;
        {
            float i0 = Gsm[pb * 66 + pu]          + xv[0].x;
            float i1 = Gsm[pb * 66 + pu + 1]      + xv[0].y;
            float f0 = Gsm[pb * 66 + 16 + pu]     + xv[1].x;
            float f1 = Gsm[pb * 66 + 16 + pu + 1] + xv[1].y;
            float g0 = Gsm[pb * 66 + 32 + pu]     + xv[2].x;
            float g1 = Gsm[pb * 66 + 32 + pu + 1] + xv[2].y;
            float o0 = Gsm[pb * 66 + 48 + pu]     + xv[3].x;
            float o1 = Gsm[pb * 66 + 48 + pu + 1] + xv[3].y;

            float c0 = sigf(f0) * cst[0] + sigf(i0) * tanhf(g0);
            float c1 = sigf(f1) * cst[1] + sigf(i1) * tanhf(g1);
            float h0 = sigf(o0) * tanhf(c0);
            float h1 = sigf(o1) * tanhf(c1);
            cst[0] = c0; cst[1] = c1;

            hpack = packbf(h0, h1);
            // swizzled store into g_hbuf (consumer LDSM expects this layout)
            *(uint32_t*)((char*)hout + (size_t)(b0 + pb) * 2048 + hswz) = hpack;
        }
        __syncthreads();

        // release: bar.sync (CTA acq/rel) -> st.release.gpu gives cumulative
        // happens-before to consumers' ld.acquire — no MEMBAR.GPU needed.
        if (tid == 0) {
            st_rel(my_flag, base + (unsigned)t + 1);
        }

        // hidden-sequence store off the critical path (after flag release;
        // LINEAR layout — consumed by proj_kernel)
        if (hs_sel) {
            __nv_bfloat16* __restrict__ hs = (hs_sel == 1) ? g_hs_a : g_hs_b;
            *(uint32_t*)(hs + ((size_t)(b0 + pb) * TT + t) * HH + j0 + pu) = hpack;
        }
    }
}

// ---------------------------------------------------------------------------
// Projection GEMM (all-bf16, cp.async 3-stage, ldmatrix, 128x128 tile):
// g_xg[M,4096] = A[M,K] @ W[4096,K]^T + b1 + b2,  M = B*T = 16384
// ---------------------------------------------------------------------------
__global__ void __launch_bounds__(256, 2)
proj_kernel(int a_sel, size_t w_off, const float* __restrict__ b1v,
            const float* __restrict__ b2v, int K)
{
    extern __shared__ __align__(16) unsigned char smem[];
    __nv_bfloat16* Asb = (__nv_bfloat16*)smem;    // [3][128][PS]
    __nv_bfloat16* Bsb = Asb + 3 * PTILE;         // [3][128][PS]
    float*         bsm = (float*)(Bsb + 3 * PTILE);

    const __nv_bfloat16* __restrict__ A =
        (a_sel == 0) ? g_xb : (a_sel == 1 ? g_hs_a : g_hs_b);
    const __nv_bfloat16* __restrict__ W = g_wb + w_off;

    const int tid  = threadIdx.x;
    const int m0   = blockIdx.y * 128;
    const int n0   = blockIdx.x * 128;
    const int warp = tid >> 5, lane = tid & 31;
    const int g    = lane >> 2, tq = lane & 3;
    const int wmw  = (warp >> 1) * 32;    // 0/32/64/96
    const int wnw  = (warp & 1) * 64;     // 0/64
    const int lrow = lane & 15;
    const int lhi  = (lane >> 4) * 8;

    if (tid < 128) bsm[tid] = b1v[n0 + tid] + b2v[n0 + tid];

    float acc[2][8][4];
#pragma unroll
    for (int i = 0; i < 2; i++)
#pragma unroll
        for (int j = 0; j < 8; j++)
#pragma unroll
            for (int q = 0; q < 4; q++) acc[i][j][q] = 0.0f;

    auto load = [&](int kc, int st) {
#pragma unroll
        for (int r = 0; r < 2; r++) {
            int lin = tid + r * 256;
            int row = lin >> 2, c8 = (lin & 3) * 8;
            cp16(smem_u32(Asb + st * PTILE + row * PS + c8),
                 A + (size_t)(m0 + row) * K + kc * 32 + c8);
            cp16(smem_u32(Bsb + st * PTILE + row * PS + c8),
                 W + (size_t)(n0 + row) * K + kc * 32 + c8);
        }
    };

    auto compute = [&](int st) {
        const __nv_bfloat16* Ab = Asb + st * PTILE;
        const __nv_bfloat16* Bb = Bsb + st * PTILE;
#pragma unroll
        for (int q = 0; q < 2; q++) {
            uint32_t af[2][4], bf4[4][4];
            ldsm4(af[0], smem_u32(Ab + (wmw + lrow) * PS + q * 16 + lhi));
            ldsm4(af[1], smem_u32(Ab + (wmw + 16 + lrow) * PS + q * 16 + lhi));
#pragma unroll
            for (int jn = 0; jn < 4; jn++)
                ldsm4(bf4[jn], smem_u32(Bb + (wnw + jn * 16 + lrow) * PS + q * 16 + lhi));
#pragma unroll
            for (int i = 0; i < 2; i++)
#pragma unroll
                for (int j8 = 0; j8 < 8; j8++)
                    mma_bf16(acc[i][j8], af[i],
                             bf4[j8 >> 1][j8 & 1], bf4[j8 >> 1][(j8 & 1) + 2]);
        }
    };

    const int nk = K / 32;
    load(0, 0); CP_COMMIT();
    load(1, 1); CP_COMMIT();
#pragma unroll 1
    for (int kc = 0; kc < nk; kc++) {
        cp_wait<1>();
        __syncthreads();
        if (kc + 2 < nk) load(kc + 2, (kc + 2) % 3);
        CP_COMMIT();
        compute(kc % 3);
    }

    // epilogue: add biases, store fp32 to g_xg
#pragma unroll
    for (int i = 0; i < 2; i++)
#pragma unroll
        for (int j8 = 0; j8 < 8; j8++) {
            int row  = m0 + wmw + i * 16 + g;
            int lcol = wnw + j8 * 8 + 2 * tq;
            int col  = n0 + lcol;
            float bb0 = bsm[lcol], bb1 = bsm[lcol + 1];
            g_xg[(size_t)row * G4 + col]           = acc[i][j8][0] + bb0;
            g_xg[(size_t)row * G4 + col + 1]       = acc[i][j8][1] + bb1;
            g_xg[(size_t)(row + 8) * G4 + col]     = acc[i][j8][2] + bb0;
            g_xg[(size_t)(row + 8) * G4 + col + 1] = acc[i][j8][3] + bb1;
        }
}

// ---------------------------------------------------------------------------
// Final FC: out[b] = dot(h_final[b,:], fc_w) + fc_b[0];  h_final = g_hbuf[0]
// (g_hbuf is swizzled: de-swizzle on read)
// ---------------------------------------------------------------------------
__global__ void fc_kernel(const float* __restrict__ fw,
                          const float* __restrict__ fb,
                          float* __restrict__ out)
{
    __shared__ float red[8];
    int b   = blockIdx.x;
    int tid = threadIdx.x;
    const uint32_t xr = (uint32_t)(b & 7) << 4;
    const uint32_t* __restrict__ hr =
        (const uint32_t*)((const char*)g_hbuf[0] + (size_t)b * 2048);

    float s = 0.0f;
    for (int j2 = tid; j2 < 512; j2 += blockDim.x) {
        uint32_t v = hr[(((uint32_t)(j2 * 4)) ^ xr) >> 2];
        __nv_bfloat16 lo, hi;
        memcpy(&lo, &v, 2);
        memcpy(&hi, (char*)&v + 2, 2);
        s += __bfloat162float(lo) * fw[2 * j2] +
             __bfloat162float(hi) * fw[2 * j2 + 1];
    }

#pragma unroll
    for (int o = 16; o > 0; o >>= 1) s += __shfl_down_sync(0xffffffffu, s, o);
    if ((tid & 31) == 0) red[tid >> 5] = s;
    __syncthreads();
    if (tid == 0) {
        float tot = 0.0f;
        for (int w = 0; w < 8; w++) tot += red[w];
        out[b] = tot + fb[0];
    }
}

// ---------------------------------------------------------------------------
// Launch sequence (graph-capturable, kernels only):
// convA, convB, (proj, persist) x3, fc
// ---------------------------------------------------------------------------
extern "C" void kernel_launch(void* const* d_in, const int* in_sizes, int n_in,
                              void* d_out, int out_size)
{
    const float* x       = (const float*)d_in[0];
    const float* w_ih[3] = { (const float*)d_in[1], (const float*)d_in[5], (const float*)d_in[9]  };
    const float* w_hh[3] = { (const float*)d_in[2], (const float*)d_in[6], (const float*)d_in[10] };
    const float* b_ih[3] = { (const float*)d_in[3], (const float*)d_in[7], (const float*)d_in[11] };
    const float* b_hh[3] = { (const float*)d_in[4], (const float*)d_in[8], (const float*)d_in[12] };
    const float* fc_w    = (const float*)d_in[13];
    const float* fc_b    = (const float*)d_in[14];
    float* out = (float*)d_out;

    cudaFuncSetAttribute(persist_kernel,
                         cudaFuncAttributeMaxDynamicSharedMemorySize, PERSIST_SMEM);
    cudaFuncSetAttribute(proj_kernel,
                         cudaFuncAttributeMaxDynamicSharedMemorySize, PROJ_SMEM);

    convA_kernel<<<(BB * TT * DIN / 4 + 255) / 256, 256>>>(x);
    convB_kernel<<<(G4 * HH / 4 + 255) / 256, 256>>>(w_ih[0], w_ih[1], w_ih[2]);

    const int    a_sel[3]  = { 0, 1, 2 };
    const int    hs_sel[3] = { 1, 2, 0 };
    const int    K_in[3]   = { DIN, HH, HH };
    const size_t w_off[3]  = { 0, (size_t)G4 * DIN, (size_t)G4 * (DIN + HH) };

    dim3 pgrid(32, 128);

    for (int l = 0; l < 3; l++) {
        proj_kernel<<<pgrid, 256, PROJ_SMEM>>>(a_sel[l], w_off[l], b_ih[l], b_hh[l], K_in[l]);
        persist_kernel<<<NCTA, 256, PERSIST_SMEM>>>(w_hh[l], hs_sel[l],
                                                    (unsigned)(l * TT));
    }
    fc_kernel<<<BB, 256>>>(fc_w, fc_b, out);
}

// round 14
// speedup vs baseline: 1.8615x; 1.0106x over previous
#include <cuda_runtime.h>
#include <cuda_bf16.h>
#include <cstdint>
#include <cstddef>

// Problem constants
#define BB   64
#define TT   256
#define DIN  256
#define HH   1024
#define G4   4096
#define NCTA 128

// persist smem layout
#define WS2  1032            // weight row stride elems (1024 + 8)
#define GSM_OFF  (64*WS2*2 + 32*1024*2)            // 197632
#define MBAR_OFF (GSM_OFF + 32*66*4)               // 206080
#define PERSIST_SMEM (MBAR_OFF + 64)               // 4 mbarriers @16B spacing

// proj smem layout
#define PS    40             // row stride elems (32 + 8)
#define PTILE (128*PS)       // elems per stage per operand
#define PROJ_SMEM (3*PTILE*2*2 + 512)

// flag padding: 64 u32 = 256B per flag -> distinct L2 slices
#define FPAD 64

// ---------------------------------------------------------------------------
// Scratch (allocation-free: __device__ globals)
// ---------------------------------------------------------------------------
__device__ __align__(128) float          g_xg[(size_t)BB * TT * G4];
__device__ __align__(128) __nv_bfloat16  g_hs_a[(size_t)BB * TT * HH];
__device__ __align__(128) __nv_bfloat16  g_hs_b[(size_t)BB * TT * HH];
__device__ __align__(128) __nv_bfloat16  g_hbuf[2][BB * HH];   // SWIZZLED layout
__device__ __align__(128) __nv_bfloat16  g_xb[(size_t)BB * TT * DIN];
__device__ __align__(128) __nv_bfloat16  g_wb[(size_t)(G4 * DIN + 2 * G4 * HH)];
__device__ __align__(128) unsigned       g_flags[NCTA * FPAD];

// ---------------------------------------------------------------------------
// helpers
// ---------------------------------------------------------------------------
__device__ __forceinline__ uint32_t packbf(float lo, float hi) {
    uint32_t r;
    asm("cvt.rn.bf16x2.f32 %0, %1, %2;" : "=r"(r) : "f"(hi), "f"(lo));
    return r;
}

__device__ __forceinline__ void mma_bf16(float c[4], const uint32_t a[4],
                                         uint32_t b0, uint32_t b1) {
    asm volatile(
        "mma.sync.aligned.m16n8k16.row.col.f32.bf16.bf16.f32 "
        "{%0,%1,%2,%3}, {%4,%5,%6,%7}, {%8,%9}, {%0,%1,%2,%3};\n"
        : "+f"(c[0]), "+f"(c[1]), "+f"(c[2]), "+f"(c[3])
        : "r"(a[0]), "r"(a[1]), "r"(a[2]), "r"(a[3]), "r"(b0), "r"(b1));
}

__device__ __forceinline__ uint32_t smem_u32(const void* p) {
    return (uint32_t)__cvta_generic_to_shared(p);
}

__device__ __forceinline__ void ldsm4(uint32_t r[4], uint32_t addr) {
    asm volatile("ldmatrix.sync.aligned.m8n8.x4.shared.b16 {%0,%1,%2,%3}, [%4];\n"
                 : "=r"(r[0]), "=r"(r[1]), "=r"(r[2]), "=r"(r[3]) : "r"(addr));
}

__device__ __forceinline__ void cp16(uint32_t daddr, const void* src) {
    asm volatile("cp.async.cg.shared.global [%0], [%1], 16;\n"
                 :: "r"(daddr), "l"(src));
}
#define CP_COMMIT() asm volatile("cp.async.commit_group;\n")
template <int N> __device__ __forceinline__ void cp_wait() {
    asm volatile("cp.async.wait_group %0;\n" :: "n"(N));
}

__device__ __forceinline__ unsigned ld_acq(const unsigned* p) {
    unsigned v;
    asm volatile("ld.acquire.gpu.u32 %0, [%1];" : "=r"(v) : "l"(p));
    return v;
}
__device__ __forceinline__ void st_rel(unsigned* p, unsigned v) {
    asm volatile("st.release.gpu.u32 [%0], %1;" :: "l"(p), "r"(v));
}

__device__ __forceinline__ void mbar_wait(uint32_t mbar, uint32_t parity) {
    asm volatile(
        "{\n\t.reg .pred P;\n\t"
        "WAIT_%=:\n\t"
        "mbarrier.try_wait.parity.shared.b64 P, [%0], %1;\n\t"
        "@!P bra WAIT_%=;\n\t}"
        :: "r"(mbar), "r"(parity) : "memory");
}

__device__ __forceinline__ float sigf(float x) { return 1.0f / (1.0f + __expf(-x)); }

// ---------------------------------------------------------------------------
// Convert stage A: x -> bf16
// ---------------------------------------------------------------------------
__global__ void convA_kernel(const float* __restrict__ x)
{
    int i = blockIdx.x * blockDim.x + threadIdx.x;
    if (i >= (BB * TT * DIN) / 4) return;
    float4 v = ((const float4*)x)[i];
    uint32_t* d = (uint32_t*)g_xb + (size_t)i * 2;
    d[0] = packbf(v.x, v.y);
    d[1] = packbf(v.z, v.w);
}

// ---------------------------------------------------------------------------
// Convert stage B: w_ih0/1/2 -> bf16, and zero the sync flags (per launch)
// ---------------------------------------------------------------------------
__global__ void convB_kernel(const float* __restrict__ w0,
                             const float* __restrict__ w1,
                             const float* __restrict__ w2)
{
    int i = blockIdx.x * blockDim.x + threadIdx.x;
    if (i < NCTA * FPAD) g_flags[i] = 0;
    if (i < (G4 * DIN) / 4) {
        float4 v = ((const float4*)w0)[i];
        uint32_t* d = (uint32_t*)g_wb + (size_t)i * 2;
        d[0] = packbf(v.x, v.y);
        d[1] = packbf(v.z, v.w);
    }
    if (i < (G4 * HH) / 4) {
        float4 v = ((const float4*)w1)[i];
        uint32_t* d = (uint32_t*)(g_wb + (size_t)G4 * DIN) + (size_t)i * 2;
        d[0] = packbf(v.x, v.y);
        d[1] = packbf(v.z, v.w);
        float4 u = ((const float4*)w2)[i];
        uint32_t* e = (uint32_t*)(g_wb + (size_t)G4 * (DIN + HH)) + (size_t)i * 2;
        e[0] = packbf(u.x, u.y);
        e[1] = packbf(u.z, u.w);
    }
}

// ---------------------------------------------------------------------------
// Persistent recurrent kernel: 128 CTAs = 2 batch-halves x 64 unit-groups.
// CTA (bh, ug): batches bh*32..+31, hidden units ug*16..+15 (64 gate cols).
// 256 threads, 8 warps (2M x 4N). Weights [64][1024] bf16 stationary in SMEM.
// h tile arrives via 4x 16KB cp.async.bulk on 4 INDEPENDENT mbarriers;
// compute of chunk kc starts as soon as its barrier flips, overlapping the
// remaining transfer with GEMM. g_hbuf uses a 16B-granular XOR swizzle
// (col ^ ((batch&7)<<4)) so the unpadded 2KB-row tile is LDSM-conflict-free.
// Monotonic padded flags; release-store ordering. t=0 skips wait/load/GEMM.
// ---------------------------------------------------------------------------
__global__ void __launch_bounds__(256, 1)
persist_kernel(const float* __restrict__ Whh, int hs_sel, unsigned base)
{
    extern __shared__ __align__(128) unsigned char smem[];
    __nv_bfloat16* Wsm = (__nv_bfloat16*)smem;            // [64][WS2]
    __nv_bfloat16* Asm = Wsm + 64 * WS2;                  // [32][1024] unpadded
    float*         Gsm = (float*)(smem + GSM_OFF);        // [32][66]
    const uint32_t mb0 = smem_u32(smem + MBAR_OFF);       // 4 mbarriers, 16B apart
    const uint32_t Abase = smem_u32(Asm);

    const int tid  = threadIdx.x;
    const int cta  = blockIdx.x;
    const int bh   = cta >> 6;
    const int ug   = cta & 63;
    const int j0   = ug * 16;
    const int b0   = bh * 32;
    const int warp = tid >> 5, lane = tid & 31;
    const int g    = lane >> 2, tq = lane & 3;
    const int wm   = (warp >> 2) * 16;    // 0 / 16
    const int wn   = (warp & 3) * 16;     // 0 / 16 / 32 / 48
    const int lrow = lane & 15;
    const int lhi  = (lane >> 4) * 8;

    // A-side ldsm addressing (swizzled, unpadded 2048B rows)
    // chunk kc holds batches kc*8..kc*8+7 (8 rows x 2048B = 16KB)
    const int      ar  = wm + lrow;
    const uint32_t Ar  = Abase + ar * 2048;
    const uint32_t xr  = (ar & 7) << 4;
    const uint32_t lb  = lhi * 2;          // 0 or 16 bytes

    // pointwise mapping: 2 adjacent units per thread
    const int pb = tid >> 3;              // batch 0..31
    const int pu = (tid & 7) * 2;         // unit pair 0,2,..,14
    const uint32_t hswz = ((uint32_t)((j0 + pu) * 2)) ^ ((uint32_t)(pb & 7) << 4);

    const unsigned* poll_p = &g_flags[(bh * 64 + (tid & 63)) * FPAD];
    unsigned* my_flag = &g_flags[(bh * 64 + ug) * FPAD];

    // ---- init mbarriers + gather/convert weights (once per layer) ----
    if (tid < 4) {
        asm volatile("mbarrier.init.shared.b64 [%0], 1;"
                     :: "r"(mb0 + tid * 16) : "memory");
    }
    for (int idx = tid; idx < 64 * 256; idx += 256) {
        int n = idx >> 8;  int k4 = (idx & 255) * 4;
        int gate = n >> 4, u = n & 15;
        float4 w = *(const float4*)(Whh + (size_t)(gate * HH + j0 + u) * HH + k4);
        uint32_t* dst = (uint32_t*)(Wsm + n * WS2 + k4);
        dst[0] = packbf(w.x, w.y);
        dst[1] = packbf(w.z, w.w);
    }
    __syncthreads();

    float cst[2] = {0.0f, 0.0f};

    for (int t = 0; t < TT; t++) {
        const __nv_bfloat16* __restrict__ hin  = g_hbuf[t & 1];
        __nv_bfloat16* __restrict__       hout = g_hbuf[(t + 1) & 1];

        // xg prefetch (float2 per gate; DRAM latency hidden behind wait/GEMM)
        float2 xv[4];
        {
            const float* xp = g_xg + ((size_t)(b0 + pb) * TT + t) * G4 + j0 + pu;
            xv[0] = *(const float2*)(xp);
            xv[1] = *(const float2*)(xp + HH);
            xv[2] = *(const float2*)(xp + 2 * HH);
            xv[3] = *(const float2*)(xp + 3 * HH);
        }

        float acc[2][4];
#pragma unroll
        for (int ns = 0; ns < 2; ns++)
#pragma unroll
            for (int q = 0; q < 4; q++) acc[ns][q] = 0.0f;

        if (t > 0) {
            // wait for all 64 producers of this batch half (padded flags)
            if (tid < 64) {
                while ((int)ld_acq(poll_p) < (int)(base + t)) {}
            }
            __syncthreads();

            // 4 independent 16KB bulk copies, one mbarrier each
            if (tid == 0) {
                const char* src = (const char*)hin + (size_t)b0 * 2048;
#pragma unroll
                for (int c = 0; c < 4; c++) {
                    uint32_t mb = mb0 + c * 16;
                    asm volatile(
                        "mbarrier.arrive.expect_tx.shared.b64 _, [%0], %1;"
                        :: "r"(mb), "r"(16384u) : "memory");
                    asm volatile(
                        "cp.async.bulk.shared::cta.global.mbarrier::complete_tx::bytes "
                        "[%0], [%1], %2, [%3];"
                        :: "r"(Abase + c * 16384), "l"(src + c * 16384),
                           "r"(16384u), "r"(mb) : "memory");
                }
            }

            // GEMM: wait chunk kc's barrier, compute while later chunks fly.
            // chunk kc = batches kc*8..+7 -> warp row block wm..wm+15 spans
            // chunks (wm/8) and (wm/8 + 1); process K fully per chunk-pair.
            // Simpler: chunks map to batch rows; our A-ldsm reads rows
            // wm+lrow (0..31). Row r is in chunk r>>3. A warp (wm fixed)
            // touches rows wm..wm+15 = chunks wm>>3 and (wm>>3)+1.
            // So: wait chunks 0,1 then compute wm=0 warps... but all warps
            // compute the same K loop over their own rows. Gate per warp:
            const unsigned par = (unsigned)((t - 1) & 1);
            // each warp waits only for the two chunks holding its rows
            {
                int c_lo = wm >> 3;             // 0 or 2
                mbar_wait(mb0 + c_lo * 16, par);
                mbar_wait(mb0 + (c_lo + 1) * 16, par);
            }
#pragma unroll 1
            for (int kc = 0; kc < 4; kc++) {
                const __nv_bfloat16* Wb = Wsm + kc * 256;
                const uint32_t Ak = Ar + kc * 512;
#pragma unroll
                for (int qp = 0; qp < 16; qp++) {
                    uint32_t af[4], bf4[4];
                    ldsm4(af, Ak + (((uint32_t)(qp * 32) + lb) ^ xr));
                    ldsm4(bf4, smem_u32(Wb + (wn + lrow) * WS2 + qp * 16 + lhi));
                    mma_bf16(acc[0], af, bf4[0], bf4[2]);
                    mma_bf16(acc[1], af, bf4[1], bf4[3]);
                }
            }

            // order generic LDSM reads before next step's async-proxy writes
            asm volatile("fence.proxy.async.shared::cta;" ::: "memory");
        }

        // gate exchange through SMEM
#pragma unroll
        for (int ns = 0; ns < 2; ns++) {
            int col = wn + ns * 8 + 2 * tq;
            int row = wm + g;
            Gsm[row * 66 + col]           = acc[ns][0];
            Gsm[row * 66 + col + 1]       = acc[ns][1];
            Gsm[(row + 8) * 66 + col]     = acc[ns][2];
            Gsm[(row + 8) * 66 + col + 1] = acc[ns][3];
        }
        __syncthreads();

        // pointwise LSTM update: 2 adjacent units (pb, j0+pu / j0+pu+1)
        uint32_t hpack;
        {
            float i0 = Gsm[pb * 66 + pu]          + xv[0].x;
            float i1 = Gsm[pb * 66 + pu + 1]      + xv[0].y;
            float f0 = Gsm[pb * 66 + 16 + pu]     + xv[1].x;
            float f1 = Gsm[pb * 66 + 16 + pu + 1] + xv[1].y;
            float g0 = Gsm[pb * 66 + 32 + pu]     + xv[2].x;
            float g1 = Gsm[pb * 66 + 32 + pu + 1] + xv[2].y;
            float o0 = Gsm[pb * 66 + 48 + pu]     + xv[3].x;
            float o1 = Gsm[pb * 66 + 48 + pu + 1] + xv[3].y;

            float c0 = sigf(f0) * cst[0] + sigf(i0) * tanhf(g0);
            float c1 = sigf(f1) * cst[1] + sigf(i1) * tanhf(g1);
            float h0 = sigf(o0) * tanhf(c0);
            float h1 = sigf(o1) * tanhf(c1);
            cst[0] = c0; cst[1] = c1;

            hpack = packbf(h0, h1);
            // swizzled store into g_hbuf (consumer LDSM expects this layout)
            *(uint32_t*)((char*)hout + (size_t)(b0 + pb) * 2048 + hswz) = hpack;
        }
        __syncthreads();

        // release: bar.sync (CTA acq/rel) -> st.release.gpu gives cumulative
        // happens-before to consumers' ld.acquire — no MEMBAR.GPU needed.
        if (tid == 0) {
            st_rel(my_flag, base + (unsigned)t + 1);
        }

        // hidden-sequence store off the critical path (after flag release;
        // LINEAR layout — consumed by proj_kernel)
        if (hs_sel) {
            __nv_bfloat16* __restrict__ hs = (hs_sel == 1) ? g_hs_a : g_hs_b;
            *(uint32_t*)(hs + ((size_t)(b0 + pb) * TT + t) * HH + j0 + pu) = hpack;
        }
    }
}

// ---------------------------------------------------------------------------
// Projection GEMM (all-bf16, cp.async 3-stage, ldmatrix, 128x128 tile):
// g_xg[M,4096] = A[M,K] @ W[4096,K]^T + b1 + b2,  M = B*T = 16384
// ---------------------------------------------------------------------------
__global__ void __launch_bounds__(256, 2)
proj_kernel(int a_sel, size_t w_off, const float* __restrict__ b1v,
            const float* __restrict__ b2v, int K)
{
    extern __shared__ __align__(16) unsigned char smem[];
    __nv_bfloat16* Asb = (__nv_bfloat16*)smem;    // [3][128][PS]
    __nv_bfloat16* Bsb = Asb + 3 * PTILE;         // [3][128][PS]
    float*         bsm = (float*)(Bsb + 3 * PTILE);

    const __nv_bfloat16* __restrict__ A =
        (a_sel == 0) ? g_xb : (a_sel == 1 ? g_hs_a : g_hs_b);
    const __nv_bfloat16* __restrict__ W = g_wb + w_off;

    const int tid  = threadIdx.x;
    const int m0   = blockIdx.y * 128;
    const int n0   = blockIdx.x * 128;
    const int warp = tid >> 5, lane = tid & 31;
    const int g    = lane >> 2, tq = lane & 3;
    const int wmw  = (warp >> 1) * 32;    // 0/32/64/96
    const int wnw  = (warp & 1) * 64;     // 0/64
    const int lrow = lane & 15;
    const int lhi  = (lane >> 4) * 8;

    if (tid < 128) bsm[tid] = b1v[n0 + tid] + b2v[n0 + tid];

    float acc[2][8][4];
#pragma unroll
    for (int i = 0; i < 2; i++)
#pragma unroll
        for (int j = 0; j < 8; j++)
#pragma unroll
            for (int q = 0; q < 4; q++) acc[i][j][q] = 0.0f;

    auto load = [&](int kc, int st) {
#pragma unroll
        for (int r = 0; r < 2; r++) {
            int lin = tid + r * 256;
            int row = lin >> 2, c8 = (lin & 3) * 8;
            cp16(smem_u32(Asb + st * PTILE + row * PS + c8),
                 A + (size_t)(m0 + row) * K + kc * 32 + c8);
            cp16(smem_u32(Bsb + st * PTILE + row * PS + c8),
                 W + (size_t)(n0 + row) * K + kc * 32 + c8);
        }
    };

    auto compute = [&](int st) {
        const __nv_bfloat16* Ab = Asb + st * PTILE;
        const __nv_bfloat16* Bb = Bsb + st * PTILE;
#pragma unroll
        for (int q = 0; q < 2; q++) {
            uint32_t af[2][4], bf4[4][4];
            ldsm4(af[0], smem_u32(Ab + (wmw + lrow) * PS + q * 16 + lhi));
            ldsm4(af[1], smem_u32(Ab + (wmw + 16 + lrow) * PS + q * 16 + lhi));
#pragma unroll
            for (int jn = 0; jn < 4; jn++)
                ldsm4(bf4[jn], smem_u32(Bb + (wnw + jn * 16 + lrow) * PS + q * 16 + lhi));
#pragma unroll
            for (int i = 0; i < 2; i++)
#pragma unroll
                for (int j8 = 0; j8 < 8; j8++)
                    mma_bf16(acc[i][j8], af[i],
                             bf4[j8 >> 1][j8 & 1], bf4[j8 >> 1][(j8 & 1) + 2]);
        }
    };

    const int nk = K / 32;
    load(0, 0); CP_COMMIT();
    load(1, 1); CP_COMMIT();
#pragma unroll 1
    for (int kc = 0; kc < nk; kc++) {
        cp_wait<1>();
        __syncthreads();
        if (kc + 2 < nk) load(kc + 2, (kc + 2) % 3);
        CP_COMMIT();
        compute(kc % 3);
    }

    // epilogue: add biases, store fp32 to g_xg
#pragma unroll
    for (int i = 0; i < 2; i++)
#pragma unroll
        for (int j8 = 0; j8 < 8; j8++) {
            int row  = m0 + wmw + i * 16 + g;
            int lcol = wnw + j8 * 8 + 2 * tq;
            int col  = n0 + lcol;
            float bb0 = bsm[lcol], bb1 = bsm[lcol + 1];
            g_xg[(size_t)row * G4 + col]           = acc[i][j8][0] + bb0;
            g_xg[(size_t)row * G4 + col + 1]       = acc[i][j8][1] + bb1;
            g_xg[(size_t)(row + 8) * G4 + col]     = acc[i][j8][2] + bb0;
            g_xg[(size_t)(row + 8) * G4 + col + 1] = acc[i][j8][3] + bb1;
        }
}

// ---------------------------------------------------------------------------
// Final FC: out[b] = dot(h_final[b,:], fc_w) + fc_b[0];  h_final = g_hbuf[0]
// (g_hbuf is swizzled: de-swizzle on read)
// ---------------------------------------------------------------------------
__global__ void fc_kernel(const float* __restrict__ fw,
                          const float* __restrict__ fb,
                          float* __restrict__ out)
{
    __shared__ float red[8];
    int b   = blockIdx.x;
    int tid = threadIdx.x;
    const uint32_t xr = (uint32_t)(b & 7) << 4;
    const uint32_t* __restrict__ hr =
        (const uint32_t*)((const char*)g_hbuf[0] + (size_t)b * 2048);

    float s = 0.0f;
    for (int j2 = tid; j2 < 512; j2 += blockDim.x) {
        uint32_t v = hr[(((uint32_t)(j2 * 4)) ^ xr) >> 2];
        __nv_bfloat16 lo, hi;
        memcpy(&lo, &v, 2);
        memcpy(&hi, (char*)&v + 2, 2);
        s += __bfloat162float(lo) * fw[2 * j2] +
             __bfloat162float(hi) * fw[2 * j2 + 1];
    }

#pragma unroll
    for (int o = 16; o > 0; o >>= 1) s += __shfl_down_sync(0xffffffffu, s, o);
    if ((tid & 31) == 0) red[tid >> 5] = s;
    __syncthreads();
    if (tid == 0) {
        float tot = 0.0f;
        for (int w = 0; w < 8; w++) tot += red[w];
        out[b] = tot + fb[0];
    }
}

// ---------------------------------------------------------------------------
// Launch sequence (graph-capturable, kernels only):
// convA, convB, (proj, persist) x3, fc
// ---------------------------------------------------------------------------
extern "C" void kernel_launch(void* const* d_in, const int* in_sizes, int n_in,
                              void* d_out, int out_size)
{
    const float* x       = (const float*)d_in[0];
    const float* w_ih[3] = { (const float*)d_in[1], (const float*)d_in[5], (const float*)d_in[9]  };
    const float* w_hh[3] = { (const float*)d_in[2], (const float*)d_in[6], (const float*)d_in[10] };
    const float* b_ih[3] = { (const float*)d_in[3], (const float*)d_in[7], (const float*)d_in[11] };
    const float* b_hh[3] = { (const float*)d_in[4], (const float*)d_in[8], (const float*)d_in[12] };
    const float* fc_w    = (const float*)d_in[13];
    const float* fc_b    = (const float*)d_in[14];
    float* out = (float*)d_out;

    cudaFuncSetAttribute(persist_kernel,
                         cudaFuncAttributeMaxDynamicSharedMemorySize, PERSIST_SMEM);
    cudaFuncSetAttribute(proj_kernel,
                         cudaFuncAttributeMaxDynamicSharedMemorySize, PROJ_SMEM);

    convA_kernel<<<(BB * TT * DIN / 4 + 255) / 256, 256>>>(x);
    convB_kernel<<<(G4 * HH / 4 + 255) / 256, 256>>>(w_ih[0], w_ih[1], w_ih[2]);

    const int    a_sel[3]  = { 0, 1, 2 };
    const int    hs_sel[3] = { 1, 2, 0 };
    const int    K_in[3]   = { DIN, HH, HH };
    const size_t w_off[3]  = { 0, (size_t)G4 * DIN, (size_t)G4 * (DIN + HH) };

    dim3 pgrid(32, 128);

    for (int l = 0; l < 3; l++) {
        proj_kernel<<<pgrid, 256, PROJ_SMEM>>>(a_sel[l], w_off[l], b_ih[l], b_hh[l], K_in[l]);
        persist_kernel<<<NCTA, 256, PERSIST_SMEM>>>(w_hh[l], hs_sel[l],
                                                    (unsigned)(l * TT));
    }
    fc_kernel<<<BB, 256>>>(fc_w, fc_b, out);
}